// round 2
// baseline (speedup 1.0000x reference)
#include <cuda_runtime.h>
#include <math.h>

// ---------------- problem constants ----------------
#define Bz   8
#define Cz   8
#define Tz   2048
#define Fz   257
#define Hz   256
#define NHz  4
#define DHz  64
#define WINz 512
#define HSz  128
#define M2   (Bz*Tz)        // 16384 rows per iteration
#define BTF  (M2*Fz)        // encoder_out elements

// ---------------- device scratch (static, no runtime alloc) ----------------
__device__ float g_lin1 [M2*Hz];
__device__ float g_q    [M2*Hz];
__device__ float g_k    [Cz*M2*Hz];
__device__ float g_v    [Cz*M2*Hz];
__device__ float g_ctx  [M2*Hz];
__device__ float g_h1pre[M2*Hz];
__device__ float g_h1   [M2*Hz];
__device__ float g_f1   [M2*WINz];
__device__ float g_hhpre[M2*Hz];
__device__ float g_hh   [M2*Hz];
__device__ float g_s1   [M2*HSz];
__device__ float g_outacc[M2*Hz];
__device__ float g_cum[M2], g_rem[M2], g_still[M2], g_pc[M2];
__device__ float g_wqkv[Hz*768];
__device__ float g_bqkv[768];
__device__ float g_gate[1];
__device__ int   g_any[1];

// ---------------- generic tiled fp32 GEMM ----------------
// C = epilogue(A[M,K] @ B[K,N] + bias (+ Res))
// AMODE: 0 = direct rows, 1 = x tensor rows (row r -> channel `chan` of x[B,C,T,F])
// QKV:   split N=768 output into q / k[chan] / v[chan]
#define BM 128
#define BN 128
#define BKk 16

template<int AMODE, bool RELU, bool HAS_RES, bool QKV>
__launch_bounds__(256)
__global__ void gemm_kernel(const float* __restrict__ A, const float* __restrict__ Bmat,
                            const float* __restrict__ bias, const float* __restrict__ Res,
                            float* __restrict__ Out0, float* __restrict__ Out1,
                            float* __restrict__ Out2,
                            int M, int N, int K, int chan, const float* gate)
{
    if (gate != nullptr && *gate < 0.5f) return;

    __shared__ float As[2][BKk][BM];
    __shared__ float Bs[2][BKk][BN];

    const int tid = threadIdx.x;
    const int bm0 = blockIdx.y * BM;
    const int bn0 = blockIdx.x * BN;

    // A-load mapping: thread -> (row alm, k-chunk alk of 8)
    const int alm = tid >> 1;
    const int alk = (tid & 1) * 8;
    const int gm_a = bm0 + alm;
    long arow;
    if (AMODE == 1) arow = ((long)(gm_a / Tz) * Cz + chan) * Tz + (gm_a % Tz);
    else            arow = gm_a;
    const float* aptr = A + arow * (long)K;

    // B-load mapping: thread -> (k rows blk, blk+8; 4 consecutive cols at bln)
    const int bln = (tid & 31) * 4;
    const int blk = tid >> 5;
    const bool n4 = ((N & 3) == 0);

    const int nt = (K + BKk - 1) / BKk;

    auto loadTiles = [&](int t, int buf) {
        const int k0 = t * BKk;
        #pragma unroll
        for (int j = 0; j < 8; j++) {
            int k = alk + j;
            float vA = 0.f;
            if (k0 + k < K) vA = aptr[k0 + k];
            As[buf][k][alm] = vA;
        }
        #pragma unroll
        for (int kk = 0; kk < 2; kk++) {
            int k  = blk + kk * 8;
            int gk = k0 + k;
            int gn = bn0 + bln;
            float v0 = 0.f, v1 = 0.f, v2 = 0.f, v3 = 0.f;
            if (gk < K) {
                const float* bp = Bmat + (long)gk * N + gn;
                if (n4 && gn + 3 < N) {
                    float4 f = *(const float4*)bp;
                    v0 = f.x; v1 = f.y; v2 = f.z; v3 = f.w;
                } else {
                    if (gn + 0 < N) v0 = bp[0];
                    if (gn + 1 < N) v1 = bp[1];
                    if (gn + 2 < N) v2 = bp[2];
                    if (gn + 3 < N) v3 = bp[3];
                }
            }
            Bs[buf][k][bln + 0] = v0; Bs[buf][k][bln + 1] = v1;
            Bs[buf][k][bln + 2] = v2; Bs[buf][k][bln + 3] = v3;
        }
    };

    const int ty = tid >> 4;
    const int tx = tid & 15;

    float acc[8][8];
    #pragma unroll
    for (int i = 0; i < 8; i++)
        #pragma unroll
        for (int j = 0; j < 8; j++) acc[i][j] = 0.f;

    loadTiles(0, 0);
    __syncthreads();

    for (int t = 0; t < nt; t++) {
        const int buf = t & 1;
        if (t + 1 < nt) loadTiles(t + 1, buf ^ 1);
        #pragma unroll
        for (int kk = 0; kk < BKk; kk++) {
            float a[8], b[8];
            #pragma unroll
            for (int i = 0; i < 8; i++) a[i] = As[buf][kk][ty * 8 + i];
            #pragma unroll
            for (int j = 0; j < 8; j++) b[j] = Bs[buf][kk][tx * 8 + j];
            #pragma unroll
            for (int i = 0; i < 8; i++)
                #pragma unroll
                for (int j = 0; j < 8; j++) acc[i][j] = fmaf(a[i], b[j], acc[i][j]);
        }
        __syncthreads();
    }

    #pragma unroll
    for (int i = 0; i < 8; i++) {
        const int gm = bm0 + ty * 8 + i;
        if (gm >= M) continue;
        #pragma unroll
        for (int j = 0; j < 8; j++) {
            const int gn = bn0 + tx * 8 + j;
            if (gn >= N) continue;
            float vv = acc[i][j] + bias[gn];
            if (HAS_RES) vv += Res[(long)gm * N + gn];
            if (RELU) vv = fmaxf(vv, 0.f);
            if (QKV) {
                if (gn < 256)       Out0[(long)gm * 256 + gn] = vv;
                else if (gn < 512)  Out1[((long)chan * M2 + gm) * 256 + (gn - 256)] = vv;
                else                Out2[((long)chan * M2 + gm) * 256 + (gn - 512)] = vv;
            } else {
                Out0[(long)gm * N + gn] = vv;
            }
        }
    }
}

// ---------------- layernorm: one warp per row of 256 ----------------
__global__ void ln_kernel(const float* __restrict__ in, const float* __restrict__ g,
                          const float* __restrict__ b, float* __restrict__ out,
                          const float* gate)
{
    if (*gate < 0.5f) return;
    const int r = blockIdx.x * 8 + (threadIdx.x >> 5);
    const int l = threadIdx.x & 31;
    const float* p = in + (long)r * Hz;

    float x[8];
    float s = 0.f;
    #pragma unroll
    for (int j = 0; j < 8; j++) { x[j] = p[l + 32 * j]; s += x[j]; }
    #pragma unroll
    for (int o = 16; o; o >>= 1) s += __shfl_xor_sync(0xffffffffu, s, o);
    const float m = s * (1.f / 256.f);

    float vs = 0.f;
    #pragma unroll
    for (int j = 0; j < 8; j++) { float d = x[j] - m; vs += d * d; }
    #pragma unroll
    for (int o = 16; o; o >>= 1) vs += __shfl_xor_sync(0xffffffffu, vs, o);
    const float inv = 1.f / sqrtf(vs * (1.f / 256.f) + 1e-5f);

    float* q = out + (long)r * Hz;
    #pragma unroll
    for (int j = 0; j < 8; j++) {
        int c = l + 32 * j;
        q[c] = (x[j] - m) * inv * g[c] + b[c];
    }
}

// ---------------- channel attention: 1 block per (b,t), 1 warp per head ----------------
__global__ void attn_kernel(const float* __restrict__ q, const float* __restrict__ k,
                            const float* __restrict__ v, float* __restrict__ ctx,
                            int cc, const float* gate)
{
    if (*gate < 0.5f) return;
    const int r = blockIdx.x;
    const int w = threadIdx.x >> 5;   // head
    const int l = threadIdx.x & 31;

    const float* qp = q + (long)r * Hz + w * DHz;
    const float q0 = qp[l * 2], q1 = qp[l * 2 + 1];

    float sc[Cz];
    for (int c = 0; c < cc; c++) {
        const float* kp = k + ((long)c * M2 + r) * Hz + w * DHz;
        float p = q0 * kp[l * 2] + q1 * kp[l * 2 + 1];
        #pragma unroll
        for (int o = 16; o; o >>= 1) p += __shfl_xor_sync(0xffffffffu, p, o);
        sc[c] = p * 0.125f;   // 1/sqrt(64)
    }
    float mx = -1e30f;
    for (int c = 0; c < cc; c++) mx = fmaxf(mx, sc[c]);
    float se = 0.f;
    for (int c = 0; c < cc; c++) { sc[c] = expf(sc[c] - mx); se += sc[c]; }
    const float invs = 1.f / se;

    float o0 = 0.f, o1 = 0.f;
    for (int c = 0; c < cc; c++) {
        const float* vp = v + ((long)c * M2 + r) * Hz + w * DHz;
        float a = sc[c] * invs;
        o0 += a * vp[l * 2];
        o1 += a * vp[l * 2 + 1];
    }
    ctx[(long)r * Hz + w * DHz + l * 2]     = o0;
    ctx[(long)r * Hz + w * DHz + l * 2 + 1] = o1;
}

// ---------------- ACT ponder update: 1 block (256 thr) per row ----------------
__global__ void ponder_kernel(const float* __restrict__ s1, const float* __restrict__ Ws2,
                              const float* __restrict__ bs2, const float* __restrict__ ps_a,
                              const float* __restrict__ ps_b, const float* __restrict__ hh,
                              float* cum, float* rem, float* still, float* pc,
                              float* __restrict__ outacc,
                              int last, const float* gate, int* anyflag)
{
    if (*gate < 0.5f) return;
    const int r = blockIdx.x;
    const int t = threadIdx.x;
    __shared__ float red[256];
    __shared__ float wgt_sh;

    float p = 0.f;
    if (!last && t < HSz) p = s1[(long)r * HSz + t] * Ws2[t];
    red[t] = p;
    __syncthreads();
    for (int o = 128; o; o >>= 1) { if (t < o) red[t] += red[t + o]; __syncthreads(); }

    if (t == 0) {
        float cur;
        if (last) cur = 1.f;
        else {
            float s = red[0] + bs2[0];
            float z = (s - ps_a[0]) / (ps_b[0] + 1e-8f);
            cur = 1.f / (1.f + expf(-z));
        }
        float cm = cum[r], st = still[r], rm = rem[r], p0 = pc[r];
        float cum_n   = cm + cur * st;
        float pc_n    = p0 + st;
        float still_n = (cum_n < 1.f - 1e-4f) ? 1.f : 0.f;
        float rem_n   = rm - cur * still_n;
        pc_n += rem_n * (1.f - still_n);
        float wgt = cur * still_n + rm * (1.f - still_n);
        cum[r] = cum_n; rem[r] = rem_n; still[r] = still_n; pc[r] = pc_n;
        if (still_n > 0.5f) *anyflag = 1;   // idempotent racy store of 1
        wgt_sh = wgt;
    }
    __syncthreads();
    const float wgt = wgt_sh;
    outacc[(long)r * Hz + t] += hh[(long)r * Hz + t] * wgt;
}

__global__ void gate_kernel(float* gate, int* any)
{
    if (threadIdx.x == 0) {
        if (*any == 0) *gate = 0.f;
        *any = 0;
    }
}

// ---------------- init / pack / pc-out ----------------
__global__ void init_kernel(float* outacc, float* cum, float* rem, float* still,
                            float* pc, float* gate, int* any)
{
    const int i = blockIdx.x * blockDim.x + threadIdx.x;
    if (i < M2 * Hz) outacc[i] = 0.f;
    if (i < M2) { cum[i] = 0.f; rem[i] = 1.f; still[i] = 1.f; pc[i] = 0.f; }
    if (i == 0) { *gate = 1.f; *any = 0; }
}

__global__ void pack_kernel(const float* Wq, const float* Wk, const float* Wv,
                            const float* bq, const float* bk, const float* bv,
                            float* w, float* b)
{
    const int i = blockIdx.x * blockDim.x + threadIdx.x;
    if (i < Hz * 768) {
        int kk = i / 768, n = i % 768;
        float vv;
        if (n < 256)      vv = Wq[kk * 256 + n];
        else if (n < 512) vv = Wk[kk * 256 + (n - 256)];
        else              vv = Wv[kk * 256 + (n - 512)];
        w[i] = vv;
    }
    if (i < 768) {
        float vv;
        if (i < 256)      vv = bq[i];
        else if (i < 512) vv = bk[i - 256];
        else              vv = bv[i - 512];
        b[i] = vv;
    }
}

__global__ void pc_out_kernel(float* out, const float* pc)
{
    const int i = blockIdx.x * blockDim.x + threadIdx.x;
    if (i < M2) out[BTF + i] = pc[i];
}

// ---------------- host launch ----------------
static float* symA(const void* s)
{
    void* p = nullptr;
    cudaGetSymbolAddress(&p, s);
    return (float*)p;
}

extern "C" void kernel_launch(void* const* d_in, const int* in_sizes, int n_in,
                              void* d_out, int out_size)
{
    const float* x     = (const float*)d_in[0];
    const float* W_in  = (const float*)d_in[1];
    const float* b_in  = (const float*)d_in[2];
    const float* W_out = (const float*)d_in[3];
    const float* b_out = (const float*)d_in[4];
    const float* Wq    = (const float*)d_in[5];
    const float* bq    = (const float*)d_in[6];
    const float* Wk    = (const float*)d_in[7];
    const float* bk    = (const float*)d_in[8];
    const float* Wv    = (const float*)d_in[9];
    const float* bv    = (const float*)d_in[10];
    const float* Wo    = (const float*)d_in[11];
    const float* bo    = (const float*)d_in[12];
    const float* ln1_g = (const float*)d_in[13];
    const float* ln1_b = (const float*)d_in[14];
    const float* Wf1   = (const float*)d_in[15];
    const float* bf1   = (const float*)d_in[16];
    const float* Wf2   = (const float*)d_in[17];
    const float* bf2   = (const float*)d_in[18];
    const float* ln2_g = (const float*)d_in[19];
    const float* ln2_b = (const float*)d_in[20];
    const float* Ws1   = (const float*)d_in[21];
    const float* bs1   = (const float*)d_in[22];
    const float* Ws2   = (const float*)d_in[23];
    const float* bs2   = (const float*)d_in[24];
    const float* ps_a  = (const float*)d_in[25];
    const float* ps_b  = (const float*)d_in[26];
    float* out = (float*)d_out;

    float* p_lin1  = symA(g_lin1);
    float* p_q     = symA(g_q);
    float* p_k     = symA(g_k);
    float* p_v     = symA(g_v);
    float* p_ctx   = symA(g_ctx);
    float* p_h1pre = symA(g_h1pre);
    float* p_h1    = symA(g_h1);
    float* p_f1    = symA(g_f1);
    float* p_hhpre = symA(g_hhpre);
    float* p_hh    = symA(g_hh);
    float* p_s1    = symA(g_s1);
    float* p_oacc  = symA(g_outacc);
    float* p_cum   = symA(g_cum);
    float* p_rem   = symA(g_rem);
    float* p_still = symA(g_still);
    float* p_pc    = symA(g_pc);
    float* p_wqkv  = symA(g_wqkv);
    float* p_bqkv  = symA(g_bqkv);
    float* p_gate  = symA(g_gate);
    int*   p_any   = (int*)symA(g_any);

    // per-replay state init (graph replays must be deterministic)
    init_kernel<<<16384, 256>>>(p_oacc, p_cum, p_rem, p_still, p_pc, p_gate, p_any);
    pack_kernel<<<768, 256>>>(Wq, Wk, Wv, bq, bk, bv, p_wqkv, p_bqkv);

    const dim3 gN256(2, 128), gN768(6, 128), gN512(4, 128), gN128(1, 128), gN257(3, 128);

    for (int ci = 0; ci < Cz; ci++) {
        // lin1 = relu(x[:,ci] @ W_in + b_in)
        gemm_kernel<1, true, false, false><<<gN256, 256>>>(
            x, W_in, b_in, nullptr, p_lin1, nullptr, nullptr,
            M2, 256, Fz, ci, p_gate);
        // q / k[ci] / v[ci] = lin1 @ [Wq|Wk|Wv] + biases
        gemm_kernel<0, false, false, true><<<gN768, 256>>>(
            p_lin1, p_wqkv, p_bqkv, nullptr, p_q, p_k, p_v,
            M2, 768, 256, ci, p_gate);
        // channel attention over cc = ci+1 channels
        attn_kernel<<<M2, 128>>>(p_q, p_k, p_v, p_ctx, ci + 1, p_gate);
        // h1 = LN(q + ctx@Wo + bo)  (residual is lin1 of current channel == q-input)
        gemm_kernel<0, false, true, false><<<gN256, 256>>>(
            p_ctx, Wo, bo, p_lin1, p_h1pre, nullptr, nullptr,
            M2, 256, 256, 0, p_gate);
        ln_kernel<<<2048, 256>>>(p_h1pre, ln1_g, ln1_b, p_h1, p_gate);
        // f = relu(h1@Wf1+bf1)@Wf2 + bf2 ; hh = LN(h1 + f)
        gemm_kernel<0, true, false, false><<<gN512, 256>>>(
            p_h1, Wf1, bf1, nullptr, p_f1, nullptr, nullptr,
            M2, 512, 256, 0, p_gate);
        gemm_kernel<0, false, true, false><<<gN256, 256>>>(
            p_f1, Wf2, bf2, p_h1, p_hhpre, nullptr, nullptr,
            M2, 256, 512, 0, p_gate);
        ln_kernel<<<2048, 256>>>(p_hhpre, ln2_g, ln2_b, p_hh, p_gate);
        // ponder: s1 = relu(hh@Ws1+bs1), cur = sigmoid(...), ACT state update
        if (ci < Cz - 1) {
            gemm_kernel<0, true, false, false><<<gN128, 256>>>(
                p_hh, Ws1, bs1, nullptr, p_s1, nullptr, nullptr,
                M2, 128, 256, 0, p_gate);
        }
        ponder_kernel<<<M2, 256>>>(p_s1, Ws2, bs2, ps_a, ps_b, p_hh,
                                   p_cum, p_rem, p_still, p_pc, p_oacc,
                                   (ci == Cz - 1) ? 1 : 0, p_gate, p_any);
        gate_kernel<<<1, 32>>>(p_gate, p_any);
    }

    // encoder_out = relu(out_acc @ W_out + b_out) -> d_out[0 : B*T*F]
    gemm_kernel<0, true, false, false><<<gN257, 256>>>(
        p_oacc, W_out, b_out, nullptr, out, nullptr, nullptr,
        M2, Fz, 256, 0, nullptr);
    // pc -> d_out[B*T*F : B*T*F + B*T]
    pc_out_kernel<<<64, 256>>>(out, p_pc);
}

// round 5
// speedup vs baseline: 1.4715x; 1.4715x over previous
#include <cuda_runtime.h>
#include <math.h>
#include <stdint.h>

// ---------------- problem constants ----------------
#define Bz   8
#define Cz   8
#define Tz   2048
#define Fz   257
#define Hz   256
#define NHz  4
#define DHz  64
#define WINz 512
#define HSz  128
#define M2   (Bz*Tz)        // 16384 rows
#define BTF  (M2*Fz)

// ---------------- device scratch ----------------
__device__ __align__(16) float g_lin1 [M2*Hz];
__device__ __align__(16) float g_q    [M2*Hz];
__device__ __align__(16) float g_k    [Cz*M2*Hz];
__device__ __align__(16) float g_v    [Cz*M2*Hz];
__device__ __align__(16) float g_ctx  [M2*Hz];
__device__ __align__(16) float g_h1pre[M2*Hz];
__device__ __align__(16) float g_h1   [M2*Hz];
__device__ __align__(16) float g_f1   [M2*WINz];
__device__ __align__(16) float g_hhpre[M2*Hz];
__device__ __align__(16) float g_hh   [M2*Hz];
__device__ __align__(16) float g_s1   [M2*HSz];
__device__ __align__(16) float g_outacc[M2*Hz];
__device__ float g_cum[M2], g_rem[M2], g_still[M2], g_pc[M2];
__device__ __align__(16) float g_bqkv[768];
__device__ float g_gate[1];
__device__ int   g_any[1];

// transposed + tf32-split weights: Bt[n][k], zero padded
__device__ __align__(16) float g_bt_in_hi [256*288],  g_bt_in_lo [256*288];
__device__ __align__(16) float g_bt_qkv_hi[768*256],  g_bt_qkv_lo[768*256];
__device__ __align__(16) float g_bt_o_hi  [256*256],  g_bt_o_lo  [256*256];
__device__ __align__(16) float g_bt_f1_hi [512*256],  g_bt_f1_lo [512*256];
__device__ __align__(16) float g_bt_f2_hi [256*512],  g_bt_f2_lo [256*512];
__device__ __align__(16) float g_bt_s1_hi [128*256],  g_bt_s1_lo [128*256];
__device__ __align__(16) float g_bt_out_hi[384*256],  g_bt_out_lo[384*256];

// ---------------- helpers ----------------
__device__ __forceinline__ uint32_t smem_u32(const void* p){
    uint32_t a;
    asm("{ .reg .u64 t; cvta.to.shared.u64 t, %1; cvt.u32.u64 %0, t; }" : "=r"(a) : "l"(p));
    return a;
}
__device__ __forceinline__ uint32_t f2tf32(float a){
    uint32_t u; asm("cvt.rna.tf32.f32 %0, %1;" : "=r"(u) : "f"(a)); return u;
}
#define CP_ASYNC16(dst, src) asm volatile("cp.async.ca.shared.global [%0], [%1], 16;" :: "r"(dst), "l"(src))
#define CP_COMMIT() asm volatile("cp.async.commit_group;" ::: "memory")
#define CP_WAIT0()  asm volatile("cp.async.wait_group 0;" ::: "memory")

__device__ __forceinline__ void mma_tf32(float& d0, float& d1, float& d2, float& d3,
                                         uint32_t a0, uint32_t a1, uint32_t a2, uint32_t a3,
                                         uint32_t b0, uint32_t b1){
    asm volatile("mma.sync.aligned.m16n8k8.row.col.f32.tf32.tf32.f32 "
        "{%0,%1,%2,%3}, {%4,%5,%6,%7}, {%8,%9}, {%0,%1,%2,%3};"
        : "+f"(d0), "+f"(d1), "+f"(d2), "+f"(d3)
        : "r"(a0), "r"(a1), "r"(a2), "r"(a3), "r"(b0), "r"(b1));
}

// ---------------- tensor GEMM via mma.sync (3xTF32) ----------------
// D[M,N] = epi(A[M,Ka] @ Bt[N,Kb]^T + bias (+Res))
// 128x128 CTA tile, BK=32 double-buffered, 8 warps of 64x32.
#define PITCH 36
#define MATF  (128*PITCH)      // 4608 floats
#define BUFF  (4*MATF)         // 18432 floats per buffer
#define SMEM_DYN (2*BUFF*4)    // 147456 bytes

template<int AMODE, bool RELU, bool HAS_RES, bool QKV>
__global__ void __launch_bounds__(256, 1)
gemm_tc(const float* __restrict__ A,
        const float* __restrict__ Bhi, const float* __restrict__ Blo,
        const float* __restrict__ bias, const float* __restrict__ Res,
        float* __restrict__ Out0, float* __restrict__ Out1, float* __restrict__ Out2,
        int N, int Ka, int Kb, int Kt, int chan, const float* gate)
{
    if (gate != nullptr && *gate < 0.5f) return;

    extern __shared__ float sm[];

    const int tid  = threadIdx.x;
    const int wid  = tid >> 5;
    const int lane = tid & 31;
    const int g    = lane >> 2;
    const int t    = lane & 3;
    const int wm   = wid & 1;        // 2 m-groups of 64
    const int wn   = wid >> 1;       // 4 n-groups of 32
    const int bm0  = blockIdx.y * 128;
    const int n0   = blockIdx.x * 128;

    float acc[4][4][4];
    #pragma unroll
    for (int i = 0; i < 4; i++)
        #pragma unroll
        for (int j = 0; j < 4; j++)
            #pragma unroll
            for (int r = 0; r < 4; r++) acc[i][j][r] = 0.f;

    // ---- tile loaders ----
    auto loadA = [&](int kt, int buf){
        const int k0 = kt * 32;
        float* AH = sm + buf * BUFF;
        float* AL = AH + MATF;
        #pragma unroll
        for (int it = 0; it < 4; it++) {
            const int idx = tid + it * 256;       // 1024 items
            const int row = idx >> 3;
            const int q   = idx & 7;
            const int k   = k0 + q * 4;
            float a0, a1, a2, a3;
            if (AMODE == 0) {
                const float4 av = *(const float4*)(A + (long)(bm0 + row) * Ka + k);
                a0 = av.x; a1 = av.y; a2 = av.z; a3 = av.w;
            } else {
                const int gm = bm0 + row;
                const long arow = ((long)(gm >> 11) * Cz + chan) * Tz + (gm & (Tz - 1));
                const float* ap = A + arow * (long)Ka;
                a0 = (k + 0 < Ka) ? ap[k + 0] : 0.f;
                a1 = (k + 1 < Ka) ? ap[k + 1] : 0.f;
                a2 = (k + 2 < Ka) ? ap[k + 2] : 0.f;
                a3 = (k + 3 < Ka) ? ap[k + 3] : 0.f;
            }
            const uint32_t h0 = f2tf32(a0), h1 = f2tf32(a1), h2 = f2tf32(a2), h3 = f2tf32(a3);
            const uint32_t l0 = f2tf32(a0 - __uint_as_float(h0));
            const uint32_t l1 = f2tf32(a1 - __uint_as_float(h1));
            const uint32_t l2 = f2tf32(a2 - __uint_as_float(h2));
            const uint32_t l3 = f2tf32(a3 - __uint_as_float(h3));
            uint4* ph = (uint4*)(AH + row * PITCH + q * 4);
            uint4* pl = (uint4*)(AL + row * PITCH + q * 4);
            *ph = make_uint4(h0, h1, h2, h3);
            *pl = make_uint4(l0, l1, l2, l3);
        }
    };
    auto loadB = [&](int kt, int buf){
        const int k0 = kt * 32;
        const uint32_t bh = smem_u32(sm + buf * BUFF + 2 * MATF);
        const uint32_t bl = bh + MATF * 4;
        #pragma unroll
        for (int it = 0; it < 4; it++) {
            const int idx = tid + it * 256;
            const int row = idx >> 3;
            const int q   = idx & 7;
            const uint32_t d = (uint32_t)((row * PITCH + q * 4) * 4);
            const long srco = (long)(n0 + row) * Kb + k0 + q * 4;
            CP_ASYNC16(bh + d, Bhi + srco);
            CP_ASYNC16(bl + d, Blo + srco);
        }
    };

    loadA(0, 0);
    loadB(0, 0);
    CP_COMMIT();

    for (int kt = 0; kt < Kt; kt++) {
        CP_WAIT0();
        __syncthreads();
        const int buf = kt & 1;
        if (kt + 1 < Kt) { loadA(kt + 1, buf ^ 1); loadB(kt + 1, buf ^ 1); CP_COMMIT(); }

        const float* AH = sm + buf * BUFF;
        const float* AL = AH + MATF;
        const float* BH = AH + 2 * MATF;
        const float* BL = AH + 3 * MATF;

        #pragma unroll
        for (int ks = 0; ks < 4; ks++) {
            const int kk = ks * 8;
            uint32_t ah[4][4], al[4][4], bh[4][2], bl[4][2];
            #pragma unroll
            for (int mt = 0; mt < 4; mt++) {
                const int r0 = wm * 64 + mt * 16 + g;
                ah[mt][0] = __float_as_uint(AH[(r0    ) * PITCH + kk + t    ]);
                ah[mt][1] = __float_as_uint(AH[(r0 + 8) * PITCH + kk + t    ]);
                ah[mt][2] = __float_as_uint(AH[(r0    ) * PITCH + kk + t + 4]);
                ah[mt][3] = __float_as_uint(AH[(r0 + 8) * PITCH + kk + t + 4]);
                al[mt][0] = __float_as_uint(AL[(r0    ) * PITCH + kk + t    ]);
                al[mt][1] = __float_as_uint(AL[(r0 + 8) * PITCH + kk + t    ]);
                al[mt][2] = __float_as_uint(AL[(r0    ) * PITCH + kk + t + 4]);
                al[mt][3] = __float_as_uint(AL[(r0 + 8) * PITCH + kk + t + 4]);
            }
            #pragma unroll
            for (int nt = 0; nt < 4; nt++) {
                const int c0 = wn * 32 + nt * 8 + g;
                bh[nt][0] = __float_as_uint(BH[c0 * PITCH + kk + t    ]);
                bh[nt][1] = __float_as_uint(BH[c0 * PITCH + kk + t + 4]);
                bl[nt][0] = __float_as_uint(BL[c0 * PITCH + kk + t    ]);
                bl[nt][1] = __float_as_uint(BL[c0 * PITCH + kk + t + 4]);
            }
            #pragma unroll
            for (int mt = 0; mt < 4; mt++)
                #pragma unroll
                for (int nt = 0; nt < 4; nt++) {
                    float* d = acc[mt][nt];
                    mma_tf32(d[0], d[1], d[2], d[3],
                             ah[mt][0], ah[mt][1], ah[mt][2], ah[mt][3],
                             bh[nt][0], bh[nt][1]);
                    mma_tf32(d[0], d[1], d[2], d[3],
                             ah[mt][0], ah[mt][1], ah[mt][2], ah[mt][3],
                             bl[nt][0], bl[nt][1]);
                    mma_tf32(d[0], d[1], d[2], d[3],
                             al[mt][0], al[mt][1], al[mt][2], al[mt][3],
                             bh[nt][0], bh[nt][1]);
                }
        }
    }

    // ---------------- epilogue (from registers) ----------------
    const bool even = ((N & 1) == 0);   // float2 stores legal only when row stride is 8B-aligned
    #pragma unroll
    for (int mt = 0; mt < 4; mt++) {
        #pragma unroll
        for (int nt = 0; nt < 4; nt++) {
            const int gn = n0 + wn * 32 + nt * 8 + 2 * t;
            if (gn >= N) continue;
            const float b0 = bias[gn];
            const float b1 = (gn + 1 < N) ? bias[gn + 1] : 0.f;
            #pragma unroll
            for (int h = 0; h < 2; h++) {
                const int gm = bm0 + wm * 64 + mt * 16 + g + h * 8;
                float v0 = acc[mt][nt][h * 2 + 0] + b0;
                float v1 = acc[mt][nt][h * 2 + 1] + b1;
                if (HAS_RES) {
                    const float* rp = Res + (long)gm * N + gn;
                    v0 += rp[0];
                    if (gn + 1 < N) v1 += rp[1];
                }
                if (RELU) { v0 = fmaxf(v0, 0.f); v1 = fmaxf(v1, 0.f); }
                if (QKV) {
                    float* dst;
                    if (gn < 256)      dst = Out0 + (long)gm * 256 + gn;
                    else if (gn < 512) dst = Out1 + ((long)chan * M2 + gm) * 256 + (gn - 256);
                    else               dst = Out2 + ((long)chan * M2 + gm) * 256 + (gn - 512);
                    *(float2*)dst = make_float2(v0, v1);
                } else if (even && gn + 1 < N) {
                    *(float2*)(Out0 + (long)gm * N + gn) = make_float2(v0, v1);
                } else {
                    Out0[(long)gm * N + gn] = v0;
                    if (gn + 1 < N) Out0[(long)gm * N + gn + 1] = v1;
                }
            }
        }
    }
}

// ---------------- transpose + tf32 split of weights ----------------
__global__ void tsplit_kernel(const float* __restrict__ W, float* __restrict__ hi,
                              float* __restrict__ lo, int K, int N, int Kpad, int Nrows)
{
    const int idx = blockIdx.x * 256 + threadIdx.x;
    if (idx >= Nrows * Kpad) return;
    const int n = idx / Kpad, k = idx % Kpad;
    float v = 0.f;
    if (k < K && n < N) v = W[(long)k * N + n];
    const uint32_t uh = f2tf32(v);
    hi[idx] = __uint_as_float(uh);
    lo[idx] = __uint_as_float(f2tf32(v - __uint_as_float(uh)));
}

// ---------------- layernorm ----------------
__global__ void ln_kernel(const float* __restrict__ in, const float* __restrict__ g,
                          const float* __restrict__ b, float* __restrict__ out,
                          const float* gate)
{
    if (*gate < 0.5f) return;
    const int r = blockIdx.x * 8 + (threadIdx.x >> 5);
    const int l = threadIdx.x & 31;
    const float* p = in + (long)r * Hz;
    float x[8]; float s = 0.f;
    #pragma unroll
    for (int j = 0; j < 8; j++) { x[j] = p[l + 32 * j]; s += x[j]; }
    #pragma unroll
    for (int o = 16; o; o >>= 1) s += __shfl_xor_sync(0xffffffffu, s, o);
    const float m = s * (1.f / 256.f);
    float vs = 0.f;
    #pragma unroll
    for (int j = 0; j < 8; j++) { const float d = x[j] - m; vs += d * d; }
    #pragma unroll
    for (int o = 16; o; o >>= 1) vs += __shfl_xor_sync(0xffffffffu, vs, o);
    const float inv = 1.f / sqrtf(vs * (1.f / 256.f) + 1e-5f);
    float* q = out + (long)r * Hz;
    #pragma unroll
    for (int j = 0; j < 8; j++) { const int c = l + 32 * j; q[c] = (x[j] - m) * inv * g[c] + b[c]; }
}

// ---------------- channel attention ----------------
__global__ void attn_kernel(const float* __restrict__ q, const float* __restrict__ k,
                            const float* __restrict__ v, float* __restrict__ ctx,
                            int cc, const float* gate)
{
    if (*gate < 0.5f) return;
    const int r = blockIdx.x;
    const int w = threadIdx.x >> 5;
    const int l = threadIdx.x & 31;
    const float* qp = q + (long)r * Hz + w * DHz;
    const float q0 = qp[l * 2], q1 = qp[l * 2 + 1];
    float sc[Cz];
    for (int c = 0; c < cc; c++) {
        const float* kp = k + ((long)c * M2 + r) * Hz + w * DHz;
        float p = q0 * kp[l * 2] + q1 * kp[l * 2 + 1];
        #pragma unroll
        for (int o = 16; o; o >>= 1) p += __shfl_xor_sync(0xffffffffu, p, o);
        sc[c] = p * 0.125f;
    }
    float mx = -1e30f;
    for (int c = 0; c < cc; c++) mx = fmaxf(mx, sc[c]);
    float se = 0.f;
    for (int c = 0; c < cc; c++) { sc[c] = expf(sc[c] - mx); se += sc[c]; }
    const float invs = 1.f / se;
    float o0 = 0.f, o1 = 0.f;
    for (int c = 0; c < cc; c++) {
        const float* vp = v + ((long)c * M2 + r) * Hz + w * DHz;
        const float a = sc[c] * invs;
        o0 += a * vp[l * 2]; o1 += a * vp[l * 2 + 1];
    }
    ctx[(long)r * Hz + w * DHz + l * 2]     = o0;
    ctx[(long)r * Hz + w * DHz + l * 2 + 1] = o1;
}

// ---------------- ACT ponder update ----------------
__global__ void ponder_kernel(const float* __restrict__ s1, const float* __restrict__ Ws2,
                              const float* __restrict__ bs2, const float* __restrict__ ps_a,
                              const float* __restrict__ ps_b, const float* __restrict__ hh,
                              float* cum, float* rem, float* still, float* pc,
                              float* __restrict__ outacc,
                              int last, const float* gate, int* anyflag)
{
    if (*gate < 0.5f) return;
    const int r = blockIdx.x;
    const int t = threadIdx.x;
    __shared__ float red[256];
    __shared__ float wgt_sh;
    float p = 0.f;
    if (!last && t < HSz) p = s1[(long)r * HSz + t] * Ws2[t];
    red[t] = p;
    __syncthreads();
    for (int o = 128; o; o >>= 1) { if (t < o) red[t] += red[t + o]; __syncthreads(); }
    if (t == 0) {
        float cur;
        if (last) cur = 1.f;
        else {
            const float s = red[0] + bs2[0];
            const float z = (s - ps_a[0]) / (ps_b[0] + 1e-8f);
            cur = 1.f / (1.f + expf(-z));
        }
        const float cm = cum[r], st = still[r], rm = rem[r], p0 = pc[r];
        const float cum_n   = cm + cur * st;
        float pc_n          = p0 + st;
        const float still_n = (cum_n < 1.f - 1e-4f) ? 1.f : 0.f;
        const float rem_n   = rm - cur * still_n;
        pc_n += rem_n * (1.f - still_n);
        const float wgt = cur * still_n + rm * (1.f - still_n);
        cum[r] = cum_n; rem[r] = rem_n; still[r] = still_n; pc[r] = pc_n;
        if (still_n > 0.5f) *anyflag = 1;
        wgt_sh = wgt;
    }
    __syncthreads();
    const float wgt = wgt_sh;
    outacc[(long)r * Hz + t] += hh[(long)r * Hz + t] * wgt;
}

__global__ void gate_kernel(float* gate, int* any)
{
    if (threadIdx.x == 0) { if (*any == 0) *gate = 0.f; *any = 0; }
}

__global__ void init_kernel(float* outacc, float* cum, float* rem, float* still,
                            float* pc, float* gate, int* any)
{
    const int i = blockIdx.x * blockDim.x + threadIdx.x;
    if (i < M2 * Hz) outacc[i] = 0.f;
    if (i < M2) { cum[i] = 0.f; rem[i] = 1.f; still[i] = 1.f; pc[i] = 0.f; }
    if (i == 0) { *gate = 1.f; *any = 0; }
}

__global__ void packb_kernel(const float* bq, const float* bk, const float* bv, float* b)
{
    const int i = blockIdx.x * 256 + threadIdx.x;
    if (i < 768) b[i] = (i < 256) ? bq[i] : ((i < 512) ? bk[i - 256] : bv[i - 512]);
}

__global__ void pc_out_kernel(float* out, const float* pc)
{
    const int i = blockIdx.x * blockDim.x + threadIdx.x;
    if (i < M2) out[BTF + i] = pc[i];
}

// ---------------- host launch ----------------
static float* symA(const void* s)
{
    void* p = nullptr;
    cudaGetSymbolAddress(&p, s);
    return (float*)p;
}

extern "C" void kernel_launch(void* const* d_in, const int* in_sizes, int n_in,
                              void* d_out, int out_size)
{
    const float* x     = (const float*)d_in[0];
    const float* W_in  = (const float*)d_in[1];
    const float* b_in  = (const float*)d_in[2];
    const float* W_out = (const float*)d_in[3];
    const float* b_out = (const float*)d_in[4];
    const float* Wq    = (const float*)d_in[5];
    const float* bq    = (const float*)d_in[6];
    const float* Wk    = (const float*)d_in[7];
    const float* bk    = (const float*)d_in[8];
    const float* Wv    = (const float*)d_in[9];
    const float* bv    = (const float*)d_in[10];
    const float* Wo    = (const float*)d_in[11];
    const float* bo    = (const float*)d_in[12];
    const float* ln1_g = (const float*)d_in[13];
    const float* ln1_b = (const float*)d_in[14];
    const float* Wf1   = (const float*)d_in[15];
    const float* bf1   = (const float*)d_in[16];
    const float* Wf2   = (const float*)d_in[17];
    const float* bf2   = (const float*)d_in[18];
    const float* ln2_g = (const float*)d_in[19];
    const float* ln2_b = (const float*)d_in[20];
    const float* Ws1   = (const float*)d_in[21];
    const float* bs1   = (const float*)d_in[22];
    const float* Ws2   = (const float*)d_in[23];
    const float* bs2   = (const float*)d_in[24];
    const float* ps_a  = (const float*)d_in[25];
    const float* ps_b  = (const float*)d_in[26];
    float* out = (float*)d_out;

    float* p_lin1  = symA(g_lin1);
    float* p_q     = symA(g_q);
    float* p_k     = symA(g_k);
    float* p_v     = symA(g_v);
    float* p_ctx   = symA(g_ctx);
    float* p_h1pre = symA(g_h1pre);
    float* p_h1    = symA(g_h1);
    float* p_f1    = symA(g_f1);
    float* p_hhpre = symA(g_hhpre);
    float* p_hh    = symA(g_hh);
    float* p_s1    = symA(g_s1);
    float* p_oacc  = symA(g_outacc);
    float* p_cum   = symA(g_cum);
    float* p_rem   = symA(g_rem);
    float* p_still = symA(g_still);
    float* p_pc    = symA(g_pc);
    float* p_bqkv  = symA(g_bqkv);
    float* p_gate  = symA(g_gate);
    int*   p_any   = (int*)symA(g_any);

    float* bt_in_h  = symA(g_bt_in_hi),  *bt_in_l  = symA(g_bt_in_lo);
    float* bt_qkv_h = symA(g_bt_qkv_hi), *bt_qkv_l = symA(g_bt_qkv_lo);
    float* bt_o_h   = symA(g_bt_o_hi),   *bt_o_l   = symA(g_bt_o_lo);
    float* bt_f1_h  = symA(g_bt_f1_hi),  *bt_f1_l  = symA(g_bt_f1_lo);
    float* bt_f2_h  = symA(g_bt_f2_hi),  *bt_f2_l  = symA(g_bt_f2_lo);
    float* bt_s1_h  = symA(g_bt_s1_hi),  *bt_s1_l  = symA(g_bt_s1_lo);
    float* bt_out_h = symA(g_bt_out_hi), *bt_out_l = symA(g_bt_out_lo);

    cudaFuncSetAttribute((const void*)gemm_tc<1, true, false, false>,
                         cudaFuncAttributeMaxDynamicSharedMemorySize, SMEM_DYN);
    cudaFuncSetAttribute((const void*)gemm_tc<0, false, false, true>,
                         cudaFuncAttributeMaxDynamicSharedMemorySize, SMEM_DYN);
    cudaFuncSetAttribute((const void*)gemm_tc<0, false, true, false>,
                         cudaFuncAttributeMaxDynamicSharedMemorySize, SMEM_DYN);
    cudaFuncSetAttribute((const void*)gemm_tc<0, true, false, false>,
                         cudaFuncAttributeMaxDynamicSharedMemorySize, SMEM_DYN);

    // per-replay state init + weight prep
    init_kernel<<<16384, 256>>>(p_oacc, p_cum, p_rem, p_still, p_pc, p_gate, p_any);
    packb_kernel<<<3, 256>>>(bq, bk, bv, p_bqkv);
    tsplit_kernel<<<(256*288 + 255)/256, 256>>>(W_in,  bt_in_h,            bt_in_l,            257, 256, 288, 256);
    tsplit_kernel<<<(256*256 + 255)/256, 256>>>(Wq,    bt_qkv_h,           bt_qkv_l,           256, 256, 256, 256);
    tsplit_kernel<<<(256*256 + 255)/256, 256>>>(Wk,    bt_qkv_h + 256*256, bt_qkv_l + 256*256, 256, 256, 256, 256);
    tsplit_kernel<<<(256*256 + 255)/256, 256>>>(Wv,    bt_qkv_h + 512*256, bt_qkv_l + 512*256, 256, 256, 256, 256);
    tsplit_kernel<<<(256*256 + 255)/256, 256>>>(Wo,    bt_o_h,             bt_o_l,             256, 256, 256, 256);
    tsplit_kernel<<<(512*256 + 255)/256, 256>>>(Wf1,   bt_f1_h,            bt_f1_l,            256, 512, 256, 512);
    tsplit_kernel<<<(256*512 + 255)/256, 256>>>(Wf2,   bt_f2_h,            bt_f2_l,            512, 256, 512, 256);
    tsplit_kernel<<<(128*256 + 255)/256, 256>>>(Ws1,   bt_s1_h,            bt_s1_l,            256, 128, 256, 128);
    tsplit_kernel<<<(384*256 + 255)/256, 256>>>(W_out, bt_out_h,           bt_out_l,           256, 257, 256, 384);

    const dim3 gN256(2, 128), gN768(6, 128), gN512(4, 128), gN128(1, 128), gN257(3, 128);

    for (int ci = 0; ci < Cz; ci++) {
        // lin1 = relu(x[:,ci] @ W_in + b_in)
        gemm_tc<1, true, false, false><<<gN256, 256, SMEM_DYN>>>(
            x, bt_in_h, bt_in_l, b_in, nullptr, p_lin1, nullptr, nullptr,
            256, 257, 288, 9, ci, p_gate);
        // q / k[ci] / v[ci]
        gemm_tc<0, false, false, true><<<gN768, 256, SMEM_DYN>>>(
            p_lin1, bt_qkv_h, bt_qkv_l, p_bqkv, nullptr, p_q, p_k, p_v,
            768, 256, 256, 8, ci, p_gate);
        attn_kernel<<<M2, 128>>>(p_q, p_k, p_v, p_ctx, ci + 1, p_gate);
        // h1 = LN(lin1 + ctx@Wo + bo)
        gemm_tc<0, false, true, false><<<gN256, 256, SMEM_DYN>>>(
            p_ctx, bt_o_h, bt_o_l, bo, p_lin1, p_h1pre, nullptr, nullptr,
            256, 256, 256, 8, 0, p_gate);
        ln_kernel<<<2048, 256>>>(p_h1pre, ln1_g, ln1_b, p_h1, p_gate);
        // f = relu(h1@Wf1+bf1)@Wf2 + bf2 ; hh = LN(h1 + f)
        gemm_tc<0, true, false, false><<<gN512, 256, SMEM_DYN>>>(
            p_h1, bt_f1_h, bt_f1_l, bf1, nullptr, p_f1, nullptr, nullptr,
            512, 256, 256, 8, 0, p_gate);
        gemm_tc<0, false, true, false><<<gN256, 256, SMEM_DYN>>>(
            p_f1, bt_f2_h, bt_f2_l, bf2, p_h1, p_hhpre, nullptr, nullptr,
            256, 512, 512, 16, 0, p_gate);
        ln_kernel<<<2048, 256>>>(p_hhpre, ln2_g, ln2_b, p_hh, p_gate);
        if (ci < Cz - 1) {
            gemm_tc<0, true, false, false><<<gN128, 256, SMEM_DYN>>>(
                p_hh, bt_s1_h, bt_s1_l, bs1, nullptr, p_s1, nullptr, nullptr,
                128, 256, 256, 8, 0, p_gate);
        }
        ponder_kernel<<<M2, 256>>>(p_s1, Ws2, bs2, ps_a, ps_b, p_hh,
                                   p_cum, p_rem, p_still, p_pc, p_oacc,
                                   (ci == Cz - 1) ? 1 : 0, p_gate, p_any);
        gate_kernel<<<1, 32>>>(p_gate, p_any);
    }

    // encoder_out = relu(out_acc @ W_out + b_out)
    gemm_tc<0, true, false, false><<<gN257, 256, SMEM_DYN>>>(
        p_oacc, bt_out_h, bt_out_l, b_out, nullptr, out, nullptr, nullptr,
        257, 256, 256, 8, 0, nullptr);
    pc_out_kernel<<<64, 256>>>(out, p_pc);
}

// round 6
// speedup vs baseline: 2.1383x; 1.4531x over previous
#include <cuda_runtime.h>
#include <cuda_fp16.h>
#include <math.h>
#include <stdint.h>

// ---------------- problem constants ----------------
#define Bz   8
#define Cz   8
#define Tz   2048
#define Fz   257
#define Hz   256
#define NHz  4
#define DHz  64
#define WINz 512
#define HSz  128
#define M2   (Bz*Tz)        // 16384 rows
#define BTF  (M2*Fz)

// ---------------- device scratch ----------------
__device__ __align__(16) float g_lin1 [M2*Hz];
__device__ __align__(16) float g_q    [M2*Hz];
__device__ __align__(16) float g_k    [Cz*M2*Hz];
__device__ __align__(16) float g_v    [Cz*M2*Hz];
__device__ __align__(16) float g_ctx  [M2*Hz];
__device__ __align__(16) float g_h1pre[M2*Hz];
__device__ __align__(16) float g_h1   [M2*Hz];
__device__ __align__(16) float g_f1   [M2*WINz];
__device__ __align__(16) float g_hhpre[M2*Hz];
__device__ __align__(16) float g_hh   [M2*Hz];
__device__ __align__(16) float g_s1   [M2*HSz];
__device__ __align__(16) float g_outacc[M2*Hz];
__device__ float g_cum[M2], g_rem[M2], g_still[M2], g_pc[M2];
__device__ __align__(16) float g_bqkv[768];
__device__ float g_gate[1];
__device__ int   g_any[1];

// transposed + fp16-split weights: Bt[n][k], zero padded
__device__ __align__(16) __half g_bt_in_hi [256*288],  g_bt_in_lo [256*288];
__device__ __align__(16) __half g_bt_qkv_hi[768*256],  g_bt_qkv_lo[768*256];
__device__ __align__(16) __half g_bt_o_hi  [256*256],  g_bt_o_lo  [256*256];
__device__ __align__(16) __half g_bt_f1_hi [512*256],  g_bt_f1_lo [512*256];
__device__ __align__(16) __half g_bt_f2_hi [256*512],  g_bt_f2_lo [256*512];
__device__ __align__(16) __half g_bt_s1_hi [128*256],  g_bt_s1_lo [128*256];
__device__ __align__(16) __half g_bt_out_hi[384*256],  g_bt_out_lo[384*256];

// ---------------- helpers ----------------
__device__ __forceinline__ uint32_t smem_u32(const void* p){
    uint32_t a;
    asm("{ .reg .u64 t; cvta.to.shared.u64 t, %1; cvt.u32.u64 %0, t; }" : "=r"(a) : "l"(p));
    return a;
}
#define CP_ASYNC16(dst, src) asm volatile("cp.async.ca.shared.global [%0], [%1], 16;" :: "r"(dst), "l"(src))
#define CP_COMMIT() asm volatile("cp.async.commit_group;" ::: "memory")
#define CP_WAIT0()  asm volatile("cp.async.wait_group 0;" ::: "memory")

__device__ __forceinline__ void mma_f16(float& d0, float& d1, float& d2, float& d3,
                                        uint32_t a0, uint32_t a1, uint32_t a2, uint32_t a3,
                                        uint32_t b0, uint32_t b1){
    asm volatile("mma.sync.aligned.m16n8k16.row.col.f32.f16.f16.f32 "
        "{%0,%1,%2,%3}, {%4,%5,%6,%7}, {%8,%9}, {%0,%1,%2,%3};"
        : "+f"(d0), "+f"(d1), "+f"(d2), "+f"(d3)
        : "r"(a0), "r"(a1), "r"(a2), "r"(a3), "r"(b0), "r"(b1));
}
__device__ __forceinline__ uint32_t pack2(__half x, __half y){
    __half2 h = __halves2half2(x, y);
    return *(uint32_t*)&h;
}

// ---------------- tensor GEMM via mma.sync (3xFP16 split) ----------------
// D[M,N] = epi(A[M,Ka] @ Bt[N,Kb]^T + bias (+Res))
// 128x128 CTA tile, BK=32 double-buffered, 8 warps of 64x32.
// smem per buffer (halves): AH 0, AL 5120, BH 10240, BL 15360 ; 128 rows x pitch 40
#define PITCH_H 40
#define MAT_H   (128*PITCH_H)    // 5120 halves
#define BUFF_H  (4*MAT_H)        // 20480 halves / buffer
#define SMEM_DYN (2*BUFF_H*2)    // 81920 bytes

template<int AMODE, bool RELU, bool HAS_RES, bool QKV>
__global__ void __launch_bounds__(256, 1)
gemm_tc(const float* __restrict__ A,
        const __half* __restrict__ Bhi, const __half* __restrict__ Blo,
        const float* __restrict__ bias, const float* __restrict__ Res,
        float* __restrict__ Out0, float* __restrict__ Out1, float* __restrict__ Out2,
        int N, int Ka, int Kb, int Kt, int chan, const float* gate)
{
    if (gate != nullptr && *gate < 0.5f) return;

    extern __shared__ __half smh[];

    const int tid  = threadIdx.x;
    const int wid  = tid >> 5;
    const int lane = tid & 31;
    const int g    = lane >> 2;
    const int t    = lane & 3;
    const int wm   = wid & 1;        // 2 m-groups of 64
    const int wn   = wid >> 1;       // 4 n-groups of 32
    const int bm0  = blockIdx.y * 128;
    const int n0   = blockIdx.x * 128;

    float acc[4][4][4];
    #pragma unroll
    for (int i = 0; i < 4; i++)
        #pragma unroll
        for (int j = 0; j < 4; j++)
            #pragma unroll
            for (int r = 0; r < 4; r++) acc[i][j][r] = 0.f;

    // ---- tile loaders ----
    auto loadA = [&](int kt, int buf){
        const int k0 = kt * 32;
        __half* AH = smh + buf * BUFF_H;
        __half* AL = AH + MAT_H;
        #pragma unroll
        for (int it = 0; it < 4; it++) {
            const int idx = tid + it * 256;       // 1024 items: 128 rows x 8 quads
            const int row = idx >> 3;
            const int q   = idx & 7;
            const int k   = k0 + q * 4;
            float a0, a1, a2, a3;
            if (AMODE == 0) {
                const float4 av = *(const float4*)(A + (long)(bm0 + row) * Ka + k);
                a0 = av.x; a1 = av.y; a2 = av.z; a3 = av.w;
            } else {
                const int gm = bm0 + row;
                const long arow = ((long)(gm >> 11) * Cz + chan) * Tz + (gm & (Tz - 1));
                const float* ap = A + arow * (long)Ka;
                a0 = (k + 0 < Ka) ? ap[k + 0] : 0.f;
                a1 = (k + 1 < Ka) ? ap[k + 1] : 0.f;
                a2 = (k + 2 < Ka) ? ap[k + 2] : 0.f;
                a3 = (k + 3 < Ka) ? ap[k + 3] : 0.f;
            }
            const __half h0 = __float2half_rn(a0), h1 = __float2half_rn(a1);
            const __half h2 = __float2half_rn(a2), h3 = __float2half_rn(a3);
            const __half l0 = __float2half_rn(a0 - __half2float(h0));
            const __half l1 = __float2half_rn(a1 - __half2float(h1));
            const __half l2 = __float2half_rn(a2 - __half2float(h2));
            const __half l3 = __float2half_rn(a3 - __half2float(h3));
            const int off = row * PITCH_H + q * 4;          // halves, 8B aligned
            uint2 sh, sl;
            sh.x = pack2(h0, h1); sh.y = pack2(h2, h3);
            sl.x = pack2(l0, l1); sl.y = pack2(l2, l3);
            *(uint2*)(AH + off) = sh;
            *(uint2*)(AL + off) = sl;
        }
    };
    auto loadB = [&](int kt, int buf){
        const int k0 = kt * 32;
        const uint32_t bh = smem_u32(smh + buf * BUFF_H + 2 * MAT_H);
        const uint32_t bl = bh + MAT_H * 2;
        #pragma unroll
        for (int it = 0; it < 2; it++) {
            const int idx = tid + it * 256;      // 512 items: 128 rows x 4 chunks of 8 halves
            const int row = idx >> 2;
            const int c   = idx & 3;
            const uint32_t d = (uint32_t)((row * PITCH_H + c * 8) * 2);   // bytes, 16B aligned
            const long srco = (long)(n0 + row) * Kb + k0 + c * 8;
            CP_ASYNC16(bh + d, Bhi + srco);
            CP_ASYNC16(bl + d, Blo + srco);
        }
    };

    loadA(0, 0);
    loadB(0, 0);
    CP_COMMIT();

    for (int kt = 0; kt < Kt; kt++) {
        CP_WAIT0();
        __syncthreads();
        const int buf = kt & 1;
        if (kt + 1 < Kt) { loadA(kt + 1, buf ^ 1); loadB(kt + 1, buf ^ 1); CP_COMMIT(); }

        const __half* AH = smh + buf * BUFF_H;
        const __half* AL = AH + MAT_H;
        const __half* BH = AH + 2 * MAT_H;
        const __half* BL = AH + 3 * MAT_H;

        #pragma unroll
        for (int ks = 0; ks < 2; ks++) {
            const int kk = ks * 16;
            uint32_t ah[4][4], al[4][4], bh[4][2], bl[4][2];
            #pragma unroll
            for (int mt = 0; mt < 4; mt++) {
                const int r0 = wm * 64 + mt * 16 + g;
                ah[mt][0] = *(const uint32_t*)(AH + (r0    ) * PITCH_H + kk + 2*t    );
                ah[mt][1] = *(const uint32_t*)(AH + (r0 + 8) * PITCH_H + kk + 2*t    );
                ah[mt][2] = *(const uint32_t*)(AH + (r0    ) * PITCH_H + kk + 2*t + 8);
                ah[mt][3] = *(const uint32_t*)(AH + (r0 + 8) * PITCH_H + kk + 2*t + 8);
                al[mt][0] = *(const uint32_t*)(AL + (r0    ) * PITCH_H + kk + 2*t    );
                al[mt][1] = *(const uint32_t*)(AL + (r0 + 8) * PITCH_H + kk + 2*t    );
                al[mt][2] = *(const uint32_t*)(AL + (r0    ) * PITCH_H + kk + 2*t + 8);
                al[mt][3] = *(const uint32_t*)(AL + (r0 + 8) * PITCH_H + kk + 2*t + 8);
            }
            #pragma unroll
            for (int nt = 0; nt < 4; nt++) {
                const int c0 = wn * 32 + nt * 8 + g;
                bh[nt][0] = *(const uint32_t*)(BH + c0 * PITCH_H + kk + 2*t    );
                bh[nt][1] = *(const uint32_t*)(BH + c0 * PITCH_H + kk + 2*t + 8);
                bl[nt][0] = *(const uint32_t*)(BL + c0 * PITCH_H + kk + 2*t    );
                bl[nt][1] = *(const uint32_t*)(BL + c0 * PITCH_H + kk + 2*t + 8);
            }
            #pragma unroll
            for (int mt = 0; mt < 4; mt++)
                #pragma unroll
                for (int nt = 0; nt < 4; nt++) {
                    float* d = acc[mt][nt];
                    mma_f16(d[0], d[1], d[2], d[3],
                            ah[mt][0], ah[mt][1], ah[mt][2], ah[mt][3],
                            bh[nt][0], bh[nt][1]);
                    mma_f16(d[0], d[1], d[2], d[3],
                            ah[mt][0], ah[mt][1], ah[mt][2], ah[mt][3],
                            bl[nt][0], bl[nt][1]);
                    mma_f16(d[0], d[1], d[2], d[3],
                            al[mt][0], al[mt][1], al[mt][2], al[mt][3],
                            bh[nt][0], bh[nt][1]);
                }
        }
    }

    // ---------------- epilogue (from registers) ----------------
    const bool even = ((N & 1) == 0);
    #pragma unroll
    for (int mt = 0; mt < 4; mt++) {
        #pragma unroll
        for (int nt = 0; nt < 4; nt++) {
            const int gn = n0 + wn * 32 + nt * 8 + 2 * t;
            if (gn >= N) continue;
            const float b0 = bias[gn];
            const float b1 = (gn + 1 < N) ? bias[gn + 1] : 0.f;
            #pragma unroll
            for (int h = 0; h < 2; h++) {
                const int gm = bm0 + wm * 64 + mt * 16 + g + h * 8;
                float v0 = acc[mt][nt][h * 2 + 0] + b0;
                float v1 = acc[mt][nt][h * 2 + 1] + b1;
                if (HAS_RES) {
                    const float* rp = Res + (long)gm * N + gn;
                    v0 += rp[0];
                    if (gn + 1 < N) v1 += rp[1];
                }
                if (RELU) { v0 = fmaxf(v0, 0.f); v1 = fmaxf(v1, 0.f); }
                if (QKV) {
                    float* dst;
                    if (gn < 256)      dst = Out0 + (long)gm * 256 + gn;
                    else if (gn < 512) dst = Out1 + ((long)chan * M2 + gm) * 256 + (gn - 256);
                    else               dst = Out2 + ((long)chan * M2 + gm) * 256 + (gn - 512);
                    *(float2*)dst = make_float2(v0, v1);
                } else if (even && gn + 1 < N) {
                    *(float2*)(Out0 + (long)gm * N + gn) = make_float2(v0, v1);
                } else {
                    Out0[(long)gm * N + gn] = v0;
                    if (gn + 1 < N) Out0[(long)gm * N + gn + 1] = v1;
                }
            }
        }
    }
}

// ---------------- transpose + fp16 split of weights ----------------
__global__ void tsplit_kernel(const float* __restrict__ W, __half* __restrict__ hi,
                              __half* __restrict__ lo, int K, int N, int Kpad, int Nrows)
{
    const int idx = blockIdx.x * 256 + threadIdx.x;
    if (idx >= Nrows * Kpad) return;
    const int n = idx / Kpad, k = idx % Kpad;
    float v = 0.f;
    if (k < K && n < N) v = W[(long)k * N + n];
    const __half h = __float2half_rn(v);
    hi[idx] = h;
    lo[idx] = __float2half_rn(v - __half2float(h));
}

// ---------------- layernorm: one warp per row of 256 ----------------
__global__ void ln_kernel(const float* __restrict__ in, const float* __restrict__ g,
                          const float* __restrict__ b, float* __restrict__ out,
                          const float* gate)
{
    if (*gate < 0.5f) return;
    const int r = blockIdx.x * 8 + (threadIdx.x >> 5);
    const int l = threadIdx.x & 31;
    const float* p = in + (long)r * Hz;
    float x[8]; float s = 0.f;
    #pragma unroll
    for (int j = 0; j < 8; j++) { x[j] = p[l + 32 * j]; s += x[j]; }
    #pragma unroll
    for (int o = 16; o; o >>= 1) s += __shfl_xor_sync(0xffffffffu, s, o);
    const float m = s * (1.f / 256.f);
    float vs = 0.f;
    #pragma unroll
    for (int j = 0; j < 8; j++) { const float d = x[j] - m; vs += d * d; }
    #pragma unroll
    for (int o = 16; o; o >>= 1) vs += __shfl_xor_sync(0xffffffffu, vs, o);
    const float inv = 1.f / sqrtf(vs * (1.f / 256.f) + 1e-5f);
    float* q = out + (long)r * Hz;
    #pragma unroll
    for (int j = 0; j < 8; j++) { const int c = l + 32 * j; q[c] = (x[j] - m) * inv * g[c] + b[c]; }
}

// ---------------- channel attention: 2 rows/block, warp = (row, head) ----------------
__global__ void attn_kernel(const float* __restrict__ q, const float* __restrict__ k,
                            const float* __restrict__ v, float* __restrict__ ctx,
                            int cc, const float* gate)
{
    if (*gate < 0.5f) return;
    const int wid = threadIdx.x >> 5;
    const int r = blockIdx.x * 2 + (wid >> 2);
    const int w = wid & 3;             // head
    const int l = threadIdx.x & 31;
    const float* qp = q + (long)r * Hz + w * DHz;
    const float q0 = qp[l * 2], q1 = qp[l * 2 + 1];
    float sc[Cz];
    for (int c = 0; c < cc; c++) {
        const float* kp = k + ((long)c * M2 + r) * Hz + w * DHz;
        float p = q0 * kp[l * 2] + q1 * kp[l * 2 + 1];
        #pragma unroll
        for (int o = 16; o; o >>= 1) p += __shfl_xor_sync(0xffffffffu, p, o);
        sc[c] = p * 0.125f;
    }
    float mx = -1e30f;
    for (int c = 0; c < cc; c++) mx = fmaxf(mx, sc[c]);
    float se = 0.f;
    for (int c = 0; c < cc; c++) { sc[c] = expf(sc[c] - mx); se += sc[c]; }
    const float invs = 1.f / se;
    float o0 = 0.f, o1 = 0.f;
    for (int c = 0; c < cc; c++) {
        const float* vp = v + ((long)c * M2 + r) * Hz + w * DHz;
        const float a = sc[c] * invs;
        o0 += a * vp[l * 2]; o1 += a * vp[l * 2 + 1];
    }
    ctx[(long)r * Hz + w * DHz + l * 2]     = o0;
    ctx[(long)r * Hz + w * DHz + l * 2 + 1] = o1;
}

// ---------------- ACT ponder update: warp per row ----------------
__global__ void ponder_kernel(const float* __restrict__ s1, const float* __restrict__ Ws2,
                              const float* __restrict__ bs2, const float* __restrict__ ps_a,
                              const float* __restrict__ ps_b, const float* __restrict__ hh,
                              float* cum, float* rem, float* still, float* pc,
                              float* __restrict__ outacc,
                              int last, const float* gate, int* anyflag)
{
    if (*gate < 0.5f) return;
    const int wid  = threadIdx.x >> 5;
    const int lane = threadIdx.x & 31;
    const int r = blockIdx.x * 8 + wid;

    float p = 0.f;
    if (!last) {
        #pragma unroll
        for (int j = 0; j < 4; j++) {
            const int c = lane + 32 * j;
            p += s1[(long)r * HSz + c] * Ws2[c];
        }
    }
    #pragma unroll
    for (int o = 16; o; o >>= 1) p += __shfl_xor_sync(0xffffffffu, p, o);

    float wgt = 0.f;
    if (lane == 0) {
        float cur;
        if (last) cur = 1.f;
        else {
            const float s = p + bs2[0];
            const float z = (s - ps_a[0]) / (ps_b[0] + 1e-8f);
            cur = 1.f / (1.f + expf(-z));
        }
        const float cm = cum[r], st = still[r], rm = rem[r], p0 = pc[r];
        const float cum_n   = cm + cur * st;
        float pc_n          = p0 + st;
        const float still_n = (cum_n < 1.f - 1e-4f) ? 1.f : 0.f;
        const float rem_n   = rm - cur * still_n;
        pc_n += rem_n * (1.f - still_n);
        wgt = cur * still_n + rm * (1.f - still_n);
        cum[r] = cum_n; rem[r] = rem_n; still[r] = still_n; pc[r] = pc_n;
        if (still_n > 0.5f) *anyflag = 1;
    }
    wgt = __shfl_sync(0xffffffffu, wgt, 0);

    float4* oa = (float4*)(outacc + (long)r * Hz);
    const float4* hp = (const float4*)(hh + (long)r * Hz);
    #pragma unroll
    for (int j = 0; j < 2; j++) {
        const int i = lane * 2 + j;
        float4 o4 = oa[i];
        const float4 h4 = hp[i];
        o4.x += h4.x * wgt; o4.y += h4.y * wgt;
        o4.z += h4.z * wgt; o4.w += h4.w * wgt;
        oa[i] = o4;
    }
}

__global__ void gate_kernel(float* gate, int* any)
{
    if (threadIdx.x == 0) { if (*any == 0) *gate = 0.f; *any = 0; }
}

__global__ void init_kernel(float* outacc, float* cum, float* rem, float* still,
                            float* pc, float* gate, int* any)
{
    const int i = blockIdx.x * blockDim.x + threadIdx.x;
    if (i < M2 * Hz) outacc[i] = 0.f;
    if (i < M2) { cum[i] = 0.f; rem[i] = 1.f; still[i] = 1.f; pc[i] = 0.f; }
    if (i == 0) { *gate = 1.f; *any = 0; }
}

__global__ void packb_kernel(const float* bq, const float* bk, const float* bv, float* b)
{
    const int i = blockIdx.x * 256 + threadIdx.x;
    if (i < 768) b[i] = (i < 256) ? bq[i] : ((i < 512) ? bk[i - 256] : bv[i - 512]);
}

__global__ void pc_out_kernel(float* out, const float* pc)
{
    const int i = blockIdx.x * blockDim.x + threadIdx.x;
    if (i < M2) out[BTF + i] = pc[i];
}

// ---------------- host launch ----------------
static void* symA(const void* s)
{
    void* p = nullptr;
    cudaGetSymbolAddress(&p, s);
    return p;
}

extern "C" void kernel_launch(void* const* d_in, const int* in_sizes, int n_in,
                              void* d_out, int out_size)
{
    const float* x     = (const float*)d_in[0];
    const float* W_in  = (const float*)d_in[1];
    const float* b_in  = (const float*)d_in[2];
    const float* W_out = (const float*)d_in[3];
    const float* b_out = (const float*)d_in[4];
    const float* Wq    = (const float*)d_in[5];
    const float* bq    = (const float*)d_in[6];
    const float* Wk    = (const float*)d_in[7];
    const float* bk    = (const float*)d_in[8];
    const float* Wv    = (const float*)d_in[9];
    const float* bv    = (const float*)d_in[10];
    const float* Wo    = (const float*)d_in[11];
    const float* bo    = (const float*)d_in[12];
    const float* ln1_g = (const float*)d_in[13];
    const float* ln1_b = (const float*)d_in[14];
    const float* Wf1   = (const float*)d_in[15];
    const float* bf1   = (const float*)d_in[16];
    const float* Wf2   = (const float*)d_in[17];
    const float* bf2   = (const float*)d_in[18];
    const float* ln2_g = (const float*)d_in[19];
    const float* ln2_b = (const float*)d_in[20];
    const float* Ws1   = (const float*)d_in[21];
    const float* bs1   = (const float*)d_in[22];
    const float* Ws2   = (const float*)d_in[23];
    const float* bs2   = (const float*)d_in[24];
    const float* ps_a  = (const float*)d_in[25];
    const float* ps_b  = (const float*)d_in[26];
    float* out = (float*)d_out;

    float* p_lin1  = (float*)symA(g_lin1);
    float* p_q     = (float*)symA(g_q);
    float* p_k     = (float*)symA(g_k);
    float* p_v     = (float*)symA(g_v);
    float* p_ctx   = (float*)symA(g_ctx);
    float* p_h1pre = (float*)symA(g_h1pre);
    float* p_h1    = (float*)symA(g_h1);
    float* p_f1    = (float*)symA(g_f1);
    float* p_hhpre = (float*)symA(g_hhpre);
    float* p_hh    = (float*)symA(g_hh);
    float* p_s1    = (float*)symA(g_s1);
    float* p_oacc  = (float*)symA(g_outacc);
    float* p_cum   = (float*)symA(g_cum);
    float* p_rem   = (float*)symA(g_rem);
    float* p_still = (float*)symA(g_still);
    float* p_pc    = (float*)symA(g_pc);
    float* p_bqkv  = (float*)symA(g_bqkv);
    float* p_gate  = (float*)symA(g_gate);
    int*   p_any   = (int*)symA(g_any);

    __half* bt_in_h  = (__half*)symA(g_bt_in_hi),  *bt_in_l  = (__half*)symA(g_bt_in_lo);
    __half* bt_qkv_h = (__half*)symA(g_bt_qkv_hi), *bt_qkv_l = (__half*)symA(g_bt_qkv_lo);
    __half* bt_o_h   = (__half*)symA(g_bt_o_hi),   *bt_o_l   = (__half*)symA(g_bt_o_lo);
    __half* bt_f1_h  = (__half*)symA(g_bt_f1_hi),  *bt_f1_l  = (__half*)symA(g_bt_f1_lo);
    __half* bt_f2_h  = (__half*)symA(g_bt_f2_hi),  *bt_f2_l  = (__half*)symA(g_bt_f2_lo);
    __half* bt_s1_h  = (__half*)symA(g_bt_s1_hi),  *bt_s1_l  = (__half*)symA(g_bt_s1_lo);
    __half* bt_out_h = (__half*)symA(g_bt_out_hi), *bt_out_l = (__half*)symA(g_bt_out_lo);

    cudaFuncSetAttribute((const void*)gemm_tc<1, true, false, false>,
                         cudaFuncAttributeMaxDynamicSharedMemorySize, SMEM_DYN);
    cudaFuncSetAttribute((const void*)gemm_tc<0, false, false, true>,
                         cudaFuncAttributeMaxDynamicSharedMemorySize, SMEM_DYN);
    cudaFuncSetAttribute((const void*)gemm_tc<0, false, true, false>,
                         cudaFuncAttributeMaxDynamicSharedMemorySize, SMEM_DYN);
    cudaFuncSetAttribute((const void*)gemm_tc<0, true, false, false>,
                         cudaFuncAttributeMaxDynamicSharedMemorySize, SMEM_DYN);

    // per-replay state init + weight prep
    init_kernel<<<16384, 256>>>(p_oacc, p_cum, p_rem, p_still, p_pc, p_gate, p_any);
    packb_kernel<<<3, 256>>>(bq, bk, bv, p_bqkv);
    tsplit_kernel<<<(256*288 + 255)/256, 256>>>(W_in,  bt_in_h,            bt_in_l,            257, 256, 288, 256);
    tsplit_kernel<<<(256*256 + 255)/256, 256>>>(Wq,    bt_qkv_h,           bt_qkv_l,           256, 256, 256, 256);
    tsplit_kernel<<<(256*256 + 255)/256, 256>>>(Wk,    bt_qkv_h + 256*256, bt_qkv_l + 256*256, 256, 256, 256, 256);
    tsplit_kernel<<<(256*256 + 255)/256, 256>>>(Wv,    bt_qkv_h + 512*256, bt_qkv_l + 512*256, 256, 256, 256, 256);
    tsplit_kernel<<<(256*256 + 255)/256, 256>>>(Wo,    bt_o_h,             bt_o_l,             256, 256, 256, 256);
    tsplit_kernel<<<(512*256 + 255)/256, 256>>>(Wf1,   bt_f1_h,            bt_f1_l,            256, 512, 256, 512);
    tsplit_kernel<<<(256*512 + 255)/256, 256>>>(Wf2,   bt_f2_h,            bt_f2_l,            512, 256, 512, 256);
    tsplit_kernel<<<(128*256 + 255)/256, 256>>>(Ws1,   bt_s1_h,            bt_s1_l,            256, 128, 256, 128);
    tsplit_kernel<<<(384*256 + 255)/256, 256>>>(W_out, bt_out_h,           bt_out_l,           256, 257, 256, 384);

    const dim3 gN256(2, 128), gN768(6, 128), gN512(4, 128), gN128(1, 128), gN257(3, 128);

    for (int ci = 0; ci < Cz; ci++) {
        // lin1 = relu(x[:,ci] @ W_in + b_in)
        gemm_tc<1, true, false, false><<<gN256, 256, SMEM_DYN>>>(
            x, bt_in_h, bt_in_l, b_in, nullptr, p_lin1, nullptr, nullptr,
            256, 257, 288, 9, ci, p_gate);
        // q / k[ci] / v[ci]
        gemm_tc<0, false, false, true><<<gN768, 256, SMEM_DYN>>>(
            p_lin1, bt_qkv_h, bt_qkv_l, p_bqkv, nullptr, p_q, p_k, p_v,
            768, 256, 256, 8, ci, p_gate);
        attn_kernel<<<8192, 256>>>(p_q, p_k, p_v, p_ctx, ci + 1, p_gate);
        // h1 = LN(lin1 + ctx@Wo + bo)
        gemm_tc<0, false, true, false><<<gN256, 256, SMEM_DYN>>>(
            p_ctx, bt_o_h, bt_o_l, bo, p_lin1, p_h1pre, nullptr, nullptr,
            256, 256, 256, 8, 0, p_gate);
        ln_kernel<<<2048, 256>>>(p_h1pre, ln1_g, ln1_b, p_h1, p_gate);
        // f = relu(h1@Wf1+bf1)@Wf2 + bf2 ; hh = LN(h1 + f)
        gemm_tc<0, true, false, false><<<gN512, 256, SMEM_DYN>>>(
            p_h1, bt_f1_h, bt_f1_l, bf1, nullptr, p_f1, nullptr, nullptr,
            512, 256, 256, 8, 0, p_gate);
        gemm_tc<0, false, true, false><<<gN256, 256, SMEM_DYN>>>(
            p_f1, bt_f2_h, bt_f2_l, bf2, p_h1, p_hhpre, nullptr, nullptr,
            256, 512, 512, 16, 0, p_gate);
        ln_kernel<<<2048, 256>>>(p_hhpre, ln2_g, ln2_b, p_hh, p_gate);
        if (ci < Cz - 1) {
            gemm_tc<0, true, false, false><<<gN128, 256, SMEM_DYN>>>(
                p_hh, bt_s1_h, bt_s1_l, bs1, nullptr, p_s1, nullptr, nullptr,
                128, 256, 256, 8, 0, p_gate);
        }
        ponder_kernel<<<2048, 256>>>(p_s1, Ws2, bs2, ps_a, ps_b, p_hh,
                                     p_cum, p_rem, p_still, p_pc, p_oacc,
                                     (ci == Cz - 1) ? 1 : 0, p_gate, p_any);
        gate_kernel<<<1, 32>>>(p_gate, p_any);
    }

    // encoder_out = relu(out_acc @ W_out + b_out)
    gemm_tc<0, true, false, false><<<gN257, 256, SMEM_DYN>>>(
        p_oacc, bt_out_h, bt_out_l, b_out, nullptr, out, nullptr, nullptr,
        257, 256, 256, 8, 0, nullptr);
    pc_out_kernel<<<64, 256>>>(out, p_pc);
}

// round 7
// speedup vs baseline: 2.7223x; 1.2731x over previous
#include <cuda_runtime.h>
#include <cuda_fp16.h>
#include <math.h>
#include <stdint.h>

// ---------------- problem constants ----------------
#define Bz   8
#define Cz   8
#define Tz   2048
#define Fz   257
#define Hz   256
#define NHz  4
#define DHz  64
#define WINz 512
#define HSz  128
#define M2   (Bz*Tz)        // 16384 rows
#define BTF  (M2*Fz)

// ---------------- device scratch ----------------
__device__ __align__(16) float g_lin1 [M2*Hz];
__device__ __align__(16) float g_q    [M2*Hz];
__device__ __align__(16) float g_k    [Cz*M2*Hz];
__device__ __align__(16) float g_v    [Cz*M2*Hz];
__device__ __align__(16) float g_ctx  [M2*Hz];
__device__ __align__(16) float g_h1pre[M2*Hz];
__device__ __align__(16) float g_h1   [M2*Hz];
__device__ __align__(16) float g_f1   [M2*WINz];
__device__ __align__(16) float g_hhpre[M2*Hz];
__device__ __align__(16) float g_hh   [M2*Hz];
__device__ __align__(16) float g_s1   [M2*HSz];
__device__ __align__(16) float g_outacc[M2*Hz];
__device__ float g_cum[M2], g_rem[M2], g_still[M2], g_pc[M2];
__device__ __align__(16) float g_bqkv[768];
__device__ float g_gate[1];
__device__ int   g_any[1];

// transposed + fp16-split weights: Bt[n][k], zero padded
__device__ __align__(16) __half g_bt_in_hi [256*288],  g_bt_in_lo [256*288];
__device__ __align__(16) __half g_bt_qkv_hi[768*256],  g_bt_qkv_lo[768*256];
__device__ __align__(16) __half g_bt_o_hi  [256*256],  g_bt_o_lo  [256*256];
__device__ __align__(16) __half g_bt_f1_hi [512*256],  g_bt_f1_lo [512*256];
__device__ __align__(16) __half g_bt_f2_hi [256*512],  g_bt_f2_lo [256*512];
__device__ __align__(16) __half g_bt_s1_hi [128*256],  g_bt_s1_lo [128*256];
__device__ __align__(16) __half g_bt_out_hi[384*256],  g_bt_out_lo[384*256];

// ---------------- helpers ----------------
__device__ __forceinline__ uint32_t smem_u32(const void* p){
    uint32_t a;
    asm("{ .reg .u64 t; cvta.to.shared.u64 t, %1; cvt.u32.u64 %0, t; }" : "=r"(a) : "l"(p));
    return a;
}
#define CP_ASYNC16(dst, src) asm volatile("cp.async.ca.shared.global [%0], [%1], 16;" :: "r"(dst), "l"(src))
#define CP_COMMIT() asm volatile("cp.async.commit_group;" ::: "memory")
#define CP_WAIT0()  asm volatile("cp.async.wait_group 0;" ::: "memory")

#define LDSM4(r0,r1,r2,r3,addr) asm volatile( \
    "ldmatrix.sync.aligned.m8n8.x4.shared.b16 {%0,%1,%2,%3}, [%4];" \
    : "=r"(r0),"=r"(r1),"=r"(r2),"=r"(r3) : "r"(addr))

__device__ __forceinline__ void mma_f16(float& d0, float& d1, float& d2, float& d3,
                                        uint32_t a0, uint32_t a1, uint32_t a2, uint32_t a3,
                                        uint32_t b0, uint32_t b1){
    asm volatile("mma.sync.aligned.m16n8k16.row.col.f32.f16.f16.f32 "
        "{%0,%1,%2,%3}, {%4,%5,%6,%7}, {%8,%9}, {%0,%1,%2,%3};"
        : "+f"(d0), "+f"(d1), "+f"(d2), "+f"(d3)
        : "r"(a0), "r"(a1), "r"(a2), "r"(a3), "r"(b0), "r"(b1));
}
__device__ __forceinline__ uint32_t pack2(__half x, __half y){
    __half2 h = __halves2half2(x, y);
    return *(uint32_t*)&h;
}

// ---------------- tensor GEMM via mma.sync (3xFP16 split) ----------------
// D[M,N] = epi(A[M,Ka] @ Bt[N,Kb]^T + bias (+Res))
// 128x128 CTA tile, BK=32 double-buffered, 8 warps of 64x32, 2 CTAs/SM.
#define PITCH_H 40
#define MAT_H   (128*PITCH_H)    // 5120 halves
#define BUFF_H  (4*MAT_H)        // 20480 halves / buffer
#define SMEM_DYN (2*BUFF_H*2)    // 81920 bytes

template<int AMODE, bool RELU, bool HAS_RES, bool QKV>
__global__ void __launch_bounds__(256, 2)
gemm_tc(const float* __restrict__ A,
        const __half* __restrict__ Bhi, const __half* __restrict__ Blo,
        const float* __restrict__ bias, const float* __restrict__ Res,
        float* __restrict__ Out0, float* __restrict__ Out1, float* __restrict__ Out2,
        int N, int Ka, int Kb, int Kt, int chan, const float* gate)
{
    if (gate != nullptr && *gate < 0.5f) return;

    extern __shared__ __half smh[];

    const int tid  = threadIdx.x;
    const int wid  = tid >> 5;
    const int lane = tid & 31;
    const int g    = lane >> 2;
    const int t    = lane & 3;
    const int lq   = lane & 7;
    const int quad = lane >> 3;
    const int wm   = wid & 1;        // 2 m-groups of 64
    const int wn   = wid >> 1;       // 4 n-groups of 32
    const int bm0  = blockIdx.y * 128;
    const int n0   = blockIdx.x * 128;

    // ldmatrix per-lane offsets (halves) within a 128 x PITCH_H matrix
    // A x4: quad0:(+0 rows,k0) quad1:(+8,k0) quad2:(+0,k8) quad3:(+8,k8)
    const int a_off = (wm * 64 + lq + (quad & 1) * 8) * PITCH_H + (quad >> 1) * 8;
    // B x4: quad0:(nt_a,k0) quad1:(nt_a,k8) quad2:(nt_b,k0) quad3:(nt_b,k8)
    const int b_off = (wn * 32 + (quad >> 1) * 8 + lq) * PITCH_H + (quad & 1) * 8;

    float acc[4][4][4];
    #pragma unroll
    for (int i = 0; i < 4; i++)
        #pragma unroll
        for (int j = 0; j < 4; j++)
            #pragma unroll
            for (int r = 0; r < 4; r++) acc[i][j][r] = 0.f;

    // ---- tile loaders ----
    auto loadA = [&](int kt, int buf){
        const int k0 = kt * 32;
        __half* AH = smh + buf * BUFF_H;
        __half* AL = AH + MAT_H;
        #pragma unroll
        for (int it = 0; it < 4; it++) {
            const int idx = tid + it * 256;       // 1024 items: 128 rows x 8 quads
            const int row = idx >> 3;
            const int q   = idx & 7;
            const int k   = k0 + q * 4;
            float a0, a1, a2, a3;
            if (AMODE == 0) {
                const float4 av = *(const float4*)(A + (long)(bm0 + row) * Ka + k);
                a0 = av.x; a1 = av.y; a2 = av.z; a3 = av.w;
            } else {
                const int gm = bm0 + row;
                const long arow = ((long)(gm >> 11) * Cz + chan) * Tz + (gm & (Tz - 1));
                const float* ap = A + arow * (long)Ka;
                a0 = (k + 0 < Ka) ? ap[k + 0] : 0.f;
                a1 = (k + 1 < Ka) ? ap[k + 1] : 0.f;
                a2 = (k + 2 < Ka) ? ap[k + 2] : 0.f;
                a3 = (k + 3 < Ka) ? ap[k + 3] : 0.f;
            }
            const __half h0 = __float2half_rn(a0), h1 = __float2half_rn(a1);
            const __half h2 = __float2half_rn(a2), h3 = __float2half_rn(a3);
            const __half l0 = __float2half_rn(a0 - __half2float(h0));
            const __half l1 = __float2half_rn(a1 - __half2float(h1));
            const __half l2 = __float2half_rn(a2 - __half2float(h2));
            const __half l3 = __float2half_rn(a3 - __half2float(h3));
            const int off = row * PITCH_H + q * 4;
            uint2 sh, sl;
            sh.x = pack2(h0, h1); sh.y = pack2(h2, h3);
            sl.x = pack2(l0, l1); sl.y = pack2(l2, l3);
            *(uint2*)(AH + off) = sh;
            *(uint2*)(AL + off) = sl;
        }
    };
    auto loadB = [&](int kt, int buf){
        const int k0 = kt * 32;
        const uint32_t bh = smem_u32(smh + buf * BUFF_H + 2 * MAT_H);
        const uint32_t bl = bh + MAT_H * 2;
        #pragma unroll
        for (int it = 0; it < 2; it++) {
            const int idx = tid + it * 256;      // 512 items: 128 rows x 4 chunks of 8 halves
            const int row = idx >> 2;
            const int c   = idx & 3;
            const uint32_t d = (uint32_t)((row * PITCH_H + c * 8) * 2);
            const long srco = (long)(n0 + row) * Kb + k0 + c * 8;
            CP_ASYNC16(bh + d, Bhi + srco);
            CP_ASYNC16(bl + d, Blo + srco);
        }
    };

    loadA(0, 0);
    loadB(0, 0);
    CP_COMMIT();

    for (int kt = 0; kt < Kt; kt++) {
        CP_WAIT0();
        __syncthreads();
        const int buf = kt & 1;
        if (kt + 1 < Kt) { loadA(kt + 1, buf ^ 1); loadB(kt + 1, buf ^ 1); CP_COMMIT(); }

        const uint32_t sb  = smem_u32(smh) + (uint32_t)buf * (BUFF_H * 2);
        const uint32_t AHb = sb;
        const uint32_t ALb = sb + MAT_H * 2;
        const uint32_t BHb = sb + 2 * (MAT_H * 2);
        const uint32_t BLb = sb + 3 * (MAT_H * 2);

        #pragma unroll
        for (int ks = 0; ks < 2; ks++) {
            const int kk = ks * 16;
            const uint32_t aoffb = (uint32_t)((a_off + kk) * 2);
            const uint32_t boffb = (uint32_t)((b_off + kk) * 2);
            #pragma unroll
            for (int ntp = 0; ntp < 2; ntp++) {
                uint32_t bh0, bh1, bh2, bh3, bl0, bl1, bl2, bl3;
                const uint32_t bstep = (uint32_t)(ntp * 16 * PITCH_H * 2);
                LDSM4(bh0, bh1, bh2, bh3, BHb + boffb + bstep);
                LDSM4(bl0, bl1, bl2, bl3, BLb + boffb + bstep);
                #pragma unroll
                for (int mt = 0; mt < 4; mt++) {
                    uint32_t ah0, ah1, ah2, ah3, al0, al1, al2, al3;
                    const uint32_t astep = (uint32_t)(mt * 16 * PITCH_H * 2);
                    LDSM4(ah0, ah1, ah2, ah3, AHb + aoffb + astep);
                    LDSM4(al0, al1, al2, al3, ALb + aoffb + astep);
                    float* d0 = acc[mt][2 * ntp];
                    float* d1 = acc[mt][2 * ntp + 1];
                    mma_f16(d0[0], d0[1], d0[2], d0[3], ah0, ah1, ah2, ah3, bh0, bh1);
                    mma_f16(d1[0], d1[1], d1[2], d1[3], ah0, ah1, ah2, ah3, bh2, bh3);
                    mma_f16(d0[0], d0[1], d0[2], d0[3], ah0, ah1, ah2, ah3, bl0, bl1);
                    mma_f16(d1[0], d1[1], d1[2], d1[3], ah0, ah1, ah2, ah3, bl2, bl3);
                    mma_f16(d0[0], d0[1], d0[2], d0[3], al0, al1, al2, al3, bh0, bh1);
                    mma_f16(d1[0], d1[1], d1[2], d1[3], al0, al1, al2, al3, bh2, bh3);
                }
            }
        }
    }

    // ---------------- epilogue (from registers) ----------------
    const bool even = ((N & 1) == 0);
    #pragma unroll
    for (int mt = 0; mt < 4; mt++) {
        #pragma unroll
        for (int nt = 0; nt < 4; nt++) {
            const int gn = n0 + wn * 32 + nt * 8 + 2 * t;
            if (gn >= N) continue;
            const float b0 = bias[gn];
            const float b1 = (gn + 1 < N) ? bias[gn + 1] : 0.f;
            #pragma unroll
            for (int h = 0; h < 2; h++) {
                const int gm = bm0 + wm * 64 + mt * 16 + g + h * 8;
                float v0 = acc[mt][nt][h * 2 + 0] + b0;
                float v1 = acc[mt][nt][h * 2 + 1] + b1;
                if (HAS_RES) {
                    const float* rp = Res + (long)gm * N + gn;
                    v0 += rp[0];
                    if (gn + 1 < N) v1 += rp[1];
                }
                if (RELU) { v0 = fmaxf(v0, 0.f); v1 = fmaxf(v1, 0.f); }
                if (QKV) {
                    float* dst;
                    if (gn < 256)      dst = Out0 + (long)gm * 256 + gn;
                    else if (gn < 512) dst = Out1 + ((long)chan * M2 + gm) * 256 + (gn - 256);
                    else               dst = Out2 + ((long)chan * M2 + gm) * 256 + (gn - 512);
                    *(float2*)dst = make_float2(v0, v1);
                } else if (even && gn + 1 < N) {
                    *(float2*)(Out0 + (long)gm * N + gn) = make_float2(v0, v1);
                } else {
                    Out0[(long)gm * N + gn] = v0;
                    if (gn + 1 < N) Out0[(long)gm * N + gn + 1] = v1;
                }
            }
        }
    }
}

// ---------------- transpose + fp16 split of weights ----------------
__global__ void tsplit_kernel(const float* __restrict__ W, __half* __restrict__ hi,
                              __half* __restrict__ lo, int K, int N, int Kpad, int Nrows)
{
    const int idx = blockIdx.x * 256 + threadIdx.x;
    if (idx >= Nrows * Kpad) return;
    const int n = idx / Kpad, k = idx % Kpad;
    float v = 0.f;
    if (k < K && n < N) v = W[(long)k * N + n];
    const __half h = __float2half_rn(v);
    hi[idx] = h;
    lo[idx] = __float2half_rn(v - __half2float(h));
}

// ---------------- layernorm: one warp per row of 256 ----------------
__global__ void ln_kernel(const float* __restrict__ in, const float* __restrict__ g,
                          const float* __restrict__ b, float* __restrict__ out,
                          const float* gate)
{
    if (*gate < 0.5f) return;
    const int r = blockIdx.x * 8 + (threadIdx.x >> 5);
    const int l = threadIdx.x & 31;
    const float* p = in + (long)r * Hz;
    float x[8]; float s = 0.f;
    #pragma unroll
    for (int j = 0; j < 8; j++) { x[j] = p[l + 32 * j]; s += x[j]; }
    #pragma unroll
    for (int o = 16; o; o >>= 1) s += __shfl_xor_sync(0xffffffffu, s, o);
    const float m = s * (1.f / 256.f);
    float vs = 0.f;
    #pragma unroll
    for (int j = 0; j < 8; j++) { const float d = x[j] - m; vs += d * d; }
    #pragma unroll
    for (int o = 16; o; o >>= 1) vs += __shfl_xor_sync(0xffffffffu, vs, o);
    const float inv = 1.f / sqrtf(vs * (1.f / 256.f) + 1e-5f);
    float* q = out + (long)r * Hz;
    #pragma unroll
    for (int j = 0; j < 8; j++) { const int c = l + 32 * j; q[c] = (x[j] - m) * inv * g[c] + b[c]; }
}

// ---------------- channel attention: 2 rows/block, warp = (row, head) ----------------
__global__ void attn_kernel(const float* __restrict__ q, const float* __restrict__ k,
                            const float* __restrict__ v, float* __restrict__ ctx,
                            int cc, const float* gate)
{
    if (*gate < 0.5f) return;
    const int wid = threadIdx.x >> 5;
    const int r = blockIdx.x * 2 + (wid >> 2);
    const int w = wid & 3;             // head
    const int l = threadIdx.x & 31;
    const float* qp = q + (long)r * Hz + w * DHz;
    const float q0 = qp[l * 2], q1 = qp[l * 2 + 1];
    float sc[Cz];
    for (int c = 0; c < cc; c++) {
        const float* kp = k + ((long)c * M2 + r) * Hz + w * DHz;
        float p = q0 * kp[l * 2] + q1 * kp[l * 2 + 1];
        #pragma unroll
        for (int o = 16; o; o >>= 1) p += __shfl_xor_sync(0xffffffffu, p, o);
        sc[c] = p * 0.125f;
    }
    float mx = -1e30f;
    for (int c = 0; c < cc; c++) mx = fmaxf(mx, sc[c]);
    float se = 0.f;
    for (int c = 0; c < cc; c++) { sc[c] = expf(sc[c] - mx); se += sc[c]; }
    const float invs = 1.f / se;
    float o0 = 0.f, o1 = 0.f;
    for (int c = 0; c < cc; c++) {
        const float* vp = v + ((long)c * M2 + r) * Hz + w * DHz;
        const float a = sc[c] * invs;
        o0 += a * vp[l * 2]; o1 += a * vp[l * 2 + 1];
    }
    ctx[(long)r * Hz + w * DHz + l * 2]     = o0;
    ctx[(long)r * Hz + w * DHz + l * 2 + 1] = o1;
}

// ---------------- ACT ponder update: warp per row ----------------
__global__ void ponder_kernel(const float* __restrict__ s1, const float* __restrict__ Ws2,
                              const float* __restrict__ bs2, const float* __restrict__ ps_a,
                              const float* __restrict__ ps_b, const float* __restrict__ hh,
                              float* cum, float* rem, float* still, float* pc,
                              float* __restrict__ outacc,
                              int last, const float* gate, int* anyflag)
{
    if (*gate < 0.5f) return;
    const int wid  = threadIdx.x >> 5;
    const int lane = threadIdx.x & 31;
    const int r = blockIdx.x * 8 + wid;

    float p = 0.f;
    if (!last) {
        #pragma unroll
        for (int j = 0; j < 4; j++) {
            const int c = lane + 32 * j;
            p += s1[(long)r * HSz + c] * Ws2[c];
        }
    }
    #pragma unroll
    for (int o = 16; o; o >>= 1) p += __shfl_xor_sync(0xffffffffu, p, o);

    float wgt = 0.f;
    if (lane == 0) {
        float cur;
        if (last) cur = 1.f;
        else {
            const float s = p + bs2[0];
            const float z = (s - ps_a[0]) / (ps_b[0] + 1e-8f);
            cur = 1.f / (1.f + expf(-z));
        }
        const float cm = cum[r], st = still[r], rm = rem[r], p0 = pc[r];
        const float cum_n   = cm + cur * st;
        float pc_n          = p0 + st;
        const float still_n = (cum_n < 1.f - 1e-4f) ? 1.f : 0.f;
        const float rem_n   = rm - cur * still_n;
        pc_n += rem_n * (1.f - still_n);
        wgt = cur * still_n + rm * (1.f - still_n);
        cum[r] = cum_n; rem[r] = rem_n; still[r] = still_n; pc[r] = pc_n;
        if (still_n > 0.5f) *anyflag = 1;
    }
    wgt = __shfl_sync(0xffffffffu, wgt, 0);

    float4* oa = (float4*)(outacc + (long)r * Hz);
    const float4* hp = (const float4*)(hh + (long)r * Hz);
    #pragma unroll
    for (int j = 0; j < 2; j++) {
        const int i = lane * 2 + j;
        float4 o4 = oa[i];
        const float4 h4 = hp[i];
        o4.x += h4.x * wgt; o4.y += h4.y * wgt;
        o4.z += h4.z * wgt; o4.w += h4.w * wgt;
        oa[i] = o4;
    }
}

__global__ void gate_kernel(float* gate, int* any)
{
    if (threadIdx.x == 0) { if (*any == 0) *gate = 0.f; *any = 0; }
}

__global__ void init_kernel(float* outacc, float* cum, float* rem, float* still,
                            float* pc, float* gate, int* any)
{
    const int i = blockIdx.x * blockDim.x + threadIdx.x;
    if (i < M2 * Hz) outacc[i] = 0.f;
    if (i < M2) { cum[i] = 0.f; rem[i] = 1.f; still[i] = 1.f; pc[i] = 0.f; }
    if (i == 0) { *gate = 1.f; *any = 0; }
}

__global__ void packb_kernel(const float* bq, const float* bk, const float* bv, float* b)
{
    const int i = blockIdx.x * 256 + threadIdx.x;
    if (i < 768) b[i] = (i < 256) ? bq[i] : ((i < 512) ? bk[i - 256] : bv[i - 512]);
}

__global__ void pc_out_kernel(float* out, const float* pc)
{
    const int i = blockIdx.x * blockDim.x + threadIdx.x;
    if (i < M2) out[BTF + i] = pc[i];
}

// ---------------- host launch ----------------
static void* symA(const void* s)
{
    void* p = nullptr;
    cudaGetSymbolAddress(&p, s);
    return p;
}

extern "C" void kernel_launch(void* const* d_in, const int* in_sizes, int n_in,
                              void* d_out, int out_size)
{
    const float* x     = (const float*)d_in[0];
    const float* W_in  = (const float*)d_in[1];
    const float* b_in  = (const float*)d_in[2];
    const float* W_out = (const float*)d_in[3];
    const float* b_out = (const float*)d_in[4];
    const float* Wq    = (const float*)d_in[5];
    const float* bq    = (const float*)d_in[6];
    const float* Wk    = (const float*)d_in[7];
    const float* bk    = (const float*)d_in[8];
    const float* Wv    = (const float*)d_in[9];
    const float* bv    = (const float*)d_in[10];
    const float* Wo    = (const float*)d_in[11];
    const float* bo    = (const float*)d_in[12];
    const float* ln1_g = (const float*)d_in[13];
    const float* ln1_b = (const float*)d_in[14];
    const float* Wf1   = (const float*)d_in[15];
    const float* bf1   = (const float*)d_in[16];
    const float* Wf2   = (const float*)d_in[17];
    const float* bf2   = (const float*)d_in[18];
    const float* ln2_g = (const float*)d_in[19];
    const float* ln2_b = (const float*)d_in[20];
    const float* Ws1   = (const float*)d_in[21];
    const float* bs1   = (const float*)d_in[22];
    const float* Ws2   = (const float*)d_in[23];
    const float* bs2   = (const float*)d_in[24];
    const float* ps_a  = (const float*)d_in[25];
    const float* ps_b  = (const float*)d_in[26];
    float* out = (float*)d_out;

    float* p_lin1  = (float*)symA(g_lin1);
    float* p_q     = (float*)symA(g_q);
    float* p_k     = (float*)symA(g_k);
    float* p_v     = (float*)symA(g_v);
    float* p_ctx   = (float*)symA(g_ctx);
    float* p_h1pre = (float*)symA(g_h1pre);
    float* p_h1    = (float*)symA(g_h1);
    float* p_f1    = (float*)symA(g_f1);
    float* p_hhpre = (float*)symA(g_hhpre);
    float* p_hh    = (float*)symA(g_hh);
    float* p_s1    = (float*)symA(g_s1);
    float* p_oacc  = (float*)symA(g_outacc);
    float* p_cum   = (float*)symA(g_cum);
    float* p_rem   = (float*)symA(g_rem);
    float* p_still = (float*)symA(g_still);
    float* p_pc    = (float*)symA(g_pc);
    float* p_bqkv  = (float*)symA(g_bqkv);
    float* p_gate  = (float*)symA(g_gate);
    int*   p_any   = (int*)symA(g_any);

    __half* bt_in_h  = (__half*)symA(g_bt_in_hi),  *bt_in_l  = (__half*)symA(g_bt_in_lo);
    __half* bt_qkv_h = (__half*)symA(g_bt_qkv_hi), *bt_qkv_l = (__half*)symA(g_bt_qkv_lo);
    __half* bt_o_h   = (__half*)symA(g_bt_o_hi),   *bt_o_l   = (__half*)symA(g_bt_o_lo);
    __half* bt_f1_h  = (__half*)symA(g_bt_f1_hi),  *bt_f1_l  = (__half*)symA(g_bt_f1_lo);
    __half* bt_f2_h  = (__half*)symA(g_bt_f2_hi),  *bt_f2_l  = (__half*)symA(g_bt_f2_lo);
    __half* bt_s1_h  = (__half*)symA(g_bt_s1_hi),  *bt_s1_l  = (__half*)symA(g_bt_s1_lo);
    __half* bt_out_h = (__half*)symA(g_bt_out_hi), *bt_out_l = (__half*)symA(g_bt_out_lo);

    cudaFuncSetAttribute((const void*)gemm_tc<1, true, false, false>,
                         cudaFuncAttributeMaxDynamicSharedMemorySize, SMEM_DYN);
    cudaFuncSetAttribute((const void*)gemm_tc<0, false, false, true>,
                         cudaFuncAttributeMaxDynamicSharedMemorySize, SMEM_DYN);
    cudaFuncSetAttribute((const void*)gemm_tc<0, false, true, false>,
                         cudaFuncAttributeMaxDynamicSharedMemorySize, SMEM_DYN);
    cudaFuncSetAttribute((const void*)gemm_tc<0, true, false, false>,
                         cudaFuncAttributeMaxDynamicSharedMemorySize, SMEM_DYN);

    // per-replay state init + weight prep
    init_kernel<<<16384, 256>>>(p_oacc, p_cum, p_rem, p_still, p_pc, p_gate, p_any);
    packb_kernel<<<3, 256>>>(bq, bk, bv, p_bqkv);
    tsplit_kernel<<<(256*288 + 255)/256, 256>>>(W_in,  bt_in_h,            bt_in_l,            257, 256, 288, 256);
    tsplit_kernel<<<(256*256 + 255)/256, 256>>>(Wq,    bt_qkv_h,           bt_qkv_l,           256, 256, 256, 256);
    tsplit_kernel<<<(256*256 + 255)/256, 256>>>(Wk,    bt_qkv_h + 256*256, bt_qkv_l + 256*256, 256, 256, 256, 256);
    tsplit_kernel<<<(256*256 + 255)/256, 256>>>(Wv,    bt_qkv_h + 512*256, bt_qkv_l + 512*256, 256, 256, 256, 256);
    tsplit_kernel<<<(256*256 + 255)/256, 256>>>(Wo,    bt_o_h,             bt_o_l,             256, 256, 256, 256);
    tsplit_kernel<<<(512*256 + 255)/256, 256>>>(Wf1,   bt_f1_h,            bt_f1_l,            256, 512, 256, 512);
    tsplit_kernel<<<(256*512 + 255)/256, 256>>>(Wf2,   bt_f2_h,            bt_f2_l,            512, 256, 512, 256);
    tsplit_kernel<<<(128*256 + 255)/256, 256>>>(Ws1,   bt_s1_h,            bt_s1_l,            256, 128, 256, 128);
    tsplit_kernel<<<(384*256 + 255)/256, 256>>>(W_out, bt_out_h,           bt_out_l,           256, 257, 256, 384);

    const dim3 gN256(2, 128), gN768(6, 128), gN512(4, 128), gN128(1, 128), gN257(3, 128);

    for (int ci = 0; ci < Cz; ci++) {
        // lin1 = relu(x[:,ci] @ W_in + b_in)
        gemm_tc<1, true, false, false><<<gN256, 256, SMEM_DYN>>>(
            x, bt_in_h, bt_in_l, b_in, nullptr, p_lin1, nullptr, nullptr,
            256, 257, 288, 9, ci, p_gate);
        // q / k[ci] / v[ci]
        gemm_tc<0, false, false, true><<<gN768, 256, SMEM_DYN>>>(
            p_lin1, bt_qkv_h, bt_qkv_l, p_bqkv, nullptr, p_q, p_k, p_v,
            768, 256, 256, 8, ci, p_gate);
        attn_kernel<<<8192, 256>>>(p_q, p_k, p_v, p_ctx, ci + 1, p_gate);
        // h1 = LN(lin1 + ctx@Wo + bo)
        gemm_tc<0, false, true, false><<<gN256, 256, SMEM_DYN>>>(
            p_ctx, bt_o_h, bt_o_l, bo, p_lin1, p_h1pre, nullptr, nullptr,
            256, 256, 256, 8, 0, p_gate);
        ln_kernel<<<2048, 256>>>(p_h1pre, ln1_g, ln1_b, p_h1, p_gate);
        // f = relu(h1@Wf1+bf1)@Wf2 + bf2 ; hh = LN(h1 + f)
        gemm_tc<0, true, false, false><<<gN512, 256, SMEM_DYN>>>(
            p_h1, bt_f1_h, bt_f1_l, bf1, nullptr, p_f1, nullptr, nullptr,
            512, 256, 256, 8, 0, p_gate);
        gemm_tc<0, false, true, false><<<gN256, 256, SMEM_DYN>>>(
            p_f1, bt_f2_h, bt_f2_l, bf2, p_h1, p_hhpre, nullptr, nullptr,
            256, 512, 512, 16, 0, p_gate);
        ln_kernel<<<2048, 256>>>(p_hhpre, ln2_g, ln2_b, p_hh, p_gate);
        if (ci < Cz - 1) {
            gemm_tc<0, true, false, false><<<gN128, 256, SMEM_DYN>>>(
                p_hh, bt_s1_h, bt_s1_l, bs1, nullptr, p_s1, nullptr, nullptr,
                128, 256, 256, 8, 0, p_gate);
        }
        ponder_kernel<<<2048, 256>>>(p_s1, Ws2, bs2, ps_a, ps_b, p_hh,
                                     p_cum, p_rem, p_still, p_pc, p_oacc,
                                     (ci == Cz - 1) ? 1 : 0, p_gate, p_any);
        gate_kernel<<<1, 32>>>(p_gate, p_any);
    }

    // encoder_out = relu(out_acc @ W_out + b_out)
    gemm_tc<0, true, false, false><<<gN257, 256, SMEM_DYN>>>(
        p_oacc, bt_out_h, bt_out_l, b_out, nullptr, out, nullptr, nullptr,
        257, 256, 256, 8, 0, nullptr);
    pc_out_kernel<<<64, 256>>>(out, p_pc);
}

// round 8
// speedup vs baseline: 2.7231x; 1.0003x over previous
#include <cuda_runtime.h>
#include <cuda_fp16.h>
#include <math.h>
#include <stdint.h>

// ---------------- problem constants ----------------
#define Bz   8
#define Cz   8
#define Tz   2048
#define Fz   257
#define Hz   256
#define NHz  4
#define DHz  64
#define WINz 512
#define HSz  128
#define M2   (Bz*Tz)        // 16384 rows
#define BTF  (M2*Fz)

// ---------------- device scratch ----------------
__device__ __align__(16) float g_lin1 [M2*Hz];     // fp32 (residual for Wo)
__device__ __align__(16) float g_q    [M2*Hz];
__device__ __align__(16) float g_k    [Cz*M2*Hz];
__device__ __align__(16) float g_v    [Cz*M2*Hz];
__device__ __align__(16) float g_h1pre[M2*Hz];
__device__ __align__(16) float g_h1   [M2*Hz];     // fp32 (residual for f2)
__device__ __align__(16) float g_hhpre[M2*Hz];
__device__ __align__(16) float g_hh   [M2*Hz];     // fp32 (ponder)
__device__ __align__(16) float g_s1   [M2*HSz];
__device__ __align__(16) float g_outacc[M2*Hz];
__device__ float g_cum[M2], g_rem[M2], g_still[M2], g_pc[M2];
__device__ __align__(16) float g_bqkv[768];
__device__ float g_gate[1];
__device__ int   g_any[1];
__device__ int   g_done[1];

// fp16 hi/lo activation copies (GEMM A operands)
__device__ __align__(16) __half g_lin1_h[M2*Hz], g_lin1_l[M2*Hz];
__device__ __align__(16) __half g_ctx_h [M2*Hz], g_ctx_l [M2*Hz];
__device__ __align__(16) __half g_h1_h  [M2*Hz], g_h1_l  [M2*Hz];
__device__ __align__(16) __half g_f1_h  [M2*WINz], g_f1_l[M2*WINz];
__device__ __align__(16) __half g_hh_h  [M2*Hz], g_hh_l  [M2*Hz];

// transposed + fp16-split weights: Bt[n][k], zero padded
__device__ __align__(16) __half g_bt_in_hi [256*288],  g_bt_in_lo [256*288];
__device__ __align__(16) __half g_bt_qkv_hi[768*256],  g_bt_qkv_lo[768*256];
__device__ __align__(16) __half g_bt_o_hi  [256*256],  g_bt_o_lo  [256*256];
__device__ __align__(16) __half g_bt_f1_hi [512*256],  g_bt_f1_lo [512*256];
__device__ __align__(16) __half g_bt_f2_hi [256*512],  g_bt_f2_lo [256*512];
__device__ __align__(16) __half g_bt_s1_hi [128*256],  g_bt_s1_lo [128*256];
__device__ __align__(16) __half g_bt_out_hi[384*256],  g_bt_out_lo[384*256];

// ---------------- helpers ----------------
__device__ __forceinline__ uint32_t smem_u32(const void* p){
    uint32_t a;
    asm("{ .reg .u64 t; cvta.to.shared.u64 t, %1; cvt.u32.u64 %0, t; }" : "=r"(a) : "l"(p));
    return a;
}
#define CP_ASYNC16(dst, src) asm volatile("cp.async.ca.shared.global [%0], [%1], 16;" :: "r"(dst), "l"(src))
#define CP_COMMIT() asm volatile("cp.async.commit_group;" ::: "memory")
#define CP_WAIT0()  asm volatile("cp.async.wait_group 0;" ::: "memory")

#define LDSM4(r0,r1,r2,r3,addr) asm volatile( \
    "ldmatrix.sync.aligned.m8n8.x4.shared.b16 {%0,%1,%2,%3}, [%4];" \
    : "=r"(r0),"=r"(r1),"=r"(r2),"=r"(r3) : "r"(addr))

__device__ __forceinline__ void mma_f16(float& d0, float& d1, float& d2, float& d3,
                                        uint32_t a0, uint32_t a1, uint32_t a2, uint32_t a3,
                                        uint32_t b0, uint32_t b1){
    asm volatile("mma.sync.aligned.m16n8k16.row.col.f32.f16.f16.f32 "
        "{%0,%1,%2,%3}, {%4,%5,%6,%7}, {%8,%9}, {%0,%1,%2,%3};"
        : "+f"(d0), "+f"(d1), "+f"(d2), "+f"(d3)
        : "r"(a0), "r"(a1), "r"(a2), "r"(a3), "r"(b0), "r"(b1));
}
__device__ __forceinline__ uint32_t pack2(__half x, __half y){
    __half2 h = __halves2half2(x, y);
    return *(uint32_t*)&h;
}

// ---------------- tensor GEMM via mma.sync (3xFP16 split) ----------------
// D[M,N] = epi(A[M,Ka] @ Bt[N,Kb]^T + bias (+Res))
// AK: 0 = A fp32 direct (convert in loader), 1 = A fp32 from x via channel, 2 = A pre-split fp16
#define PITCH_H 40
#define MAT_H   (128*PITCH_H)    // 5120 halves
#define BUFF_H  (4*MAT_H)        // 20480 halves / buffer
#define SMEM_DYN (2*BUFF_H*2)    // 81920 bytes

template<int AK, bool RELU, bool HAS_RES, bool QKV, bool OUT32, bool OUT16>
__global__ void __launch_bounds__(256, 2)
gemm_tc(const float* __restrict__ Af,
        const __half* __restrict__ Ah, const __half* __restrict__ Al,
        const __half* __restrict__ Bhi, const __half* __restrict__ Blo,
        const float* __restrict__ bias, const float* __restrict__ Res,
        float* __restrict__ Out0, float* __restrict__ Out1, float* __restrict__ Out2,
        __half* __restrict__ O16h, __half* __restrict__ O16l,
        int N, int Ka, int Kb, int Kt, int chan, const float* gate)
{
    if (gate != nullptr && *gate < 0.5f) return;

    extern __shared__ __half smh[];

    const int tid  = threadIdx.x;
    const int wid  = tid >> 5;
    const int lane = tid & 31;
    const int g    = lane >> 2;
    const int t    = lane & 3;
    const int lq   = lane & 7;
    const int quad = lane >> 3;
    const int wm   = wid & 1;
    const int wn   = wid >> 1;
    const int bm0  = blockIdx.y * 128;
    const int n0   = blockIdx.x * 128;

    const int a_off = (wm * 64 + lq + (quad & 1) * 8) * PITCH_H + (quad >> 1) * 8;
    const int b_off = (wn * 32 + (quad >> 1) * 8 + lq) * PITCH_H + (quad & 1) * 8;

    float acc[4][4][4];
    #pragma unroll
    for (int i = 0; i < 4; i++)
        #pragma unroll
        for (int j = 0; j < 4; j++)
            #pragma unroll
            for (int r = 0; r < 4; r++) acc[i][j][r] = 0.f;

    auto loadA = [&](int kt, int buf){
        const int k0 = kt * 32;
        if (AK == 2) {
            const uint32_t ah = smem_u32(smh + buf * BUFF_H);
            const uint32_t al = ah + MAT_H * 2;
            #pragma unroll
            for (int it = 0; it < 2; it++) {
                const int idx = tid + it * 256;      // 512: 128 rows x 4 chunks of 8 halves
                const int row = idx >> 2;
                const int c   = idx & 3;
                const uint32_t d = (uint32_t)((row * PITCH_H + c * 8) * 2);
                const long srco = (long)(bm0 + row) * Ka + k0 + c * 8;
                CP_ASYNC16(ah + d, Ah + srco);
                CP_ASYNC16(al + d, Al + srco);
            }
        } else {
            __half* AH = smh + buf * BUFF_H;
            __half* AL = AH + MAT_H;
            #pragma unroll
            for (int it = 0; it < 4; it++) {
                const int idx = tid + it * 256;
                const int row = idx >> 3;
                const int q   = idx & 7;
                const int k   = k0 + q * 4;
                float a0, a1, a2, a3;
                if (AK == 0) {
                    const float4 av = *(const float4*)(Af + (long)(bm0 + row) * Ka + k);
                    a0 = av.x; a1 = av.y; a2 = av.z; a3 = av.w;
                } else {
                    const int gm = bm0 + row;
                    const long arow = ((long)(gm >> 11) * Cz + chan) * Tz + (gm & (Tz - 1));
                    const float* ap = Af + arow * (long)Ka;
                    a0 = (k + 0 < Ka) ? ap[k + 0] : 0.f;
                    a1 = (k + 1 < Ka) ? ap[k + 1] : 0.f;
                    a2 = (k + 2 < Ka) ? ap[k + 2] : 0.f;
                    a3 = (k + 3 < Ka) ? ap[k + 3] : 0.f;
                }
                const __half h0 = __float2half_rn(a0), h1 = __float2half_rn(a1);
                const __half h2 = __float2half_rn(a2), h3 = __float2half_rn(a3);
                const __half l0 = __float2half_rn(a0 - __half2float(h0));
                const __half l1 = __float2half_rn(a1 - __half2float(h1));
                const __half l2 = __float2half_rn(a2 - __half2float(h2));
                const __half l3 = __float2half_rn(a3 - __half2float(h3));
                const int off = row * PITCH_H + q * 4;
                uint2 sh, sl;
                sh.x = pack2(h0, h1); sh.y = pack2(h2, h3);
                sl.x = pack2(l0, l1); sl.y = pack2(l2, l3);
                *(uint2*)(AH + off) = sh;
                *(uint2*)(AL + off) = sl;
            }
        }
    };
    auto loadB = [&](int kt, int buf){
        const int k0 = kt * 32;
        const uint32_t bh = smem_u32(smh + buf * BUFF_H + 2 * MAT_H);
        const uint32_t bl = bh + MAT_H * 2;
        #pragma unroll
        for (int it = 0; it < 2; it++) {
            const int idx = tid + it * 256;
            const int row = idx >> 2;
            const int c   = idx & 3;
            const uint32_t d = (uint32_t)((row * PITCH_H + c * 8) * 2);
            const long srco = (long)(n0 + row) * Kb + k0 + c * 8;
            CP_ASYNC16(bh + d, Bhi + srco);
            CP_ASYNC16(bl + d, Blo + srco);
        }
    };

    loadA(0, 0);
    loadB(0, 0);
    CP_COMMIT();

    for (int kt = 0; kt < Kt; kt++) {
        CP_WAIT0();
        __syncthreads();
        const int buf = kt & 1;
        if (kt + 1 < Kt) { loadA(kt + 1, buf ^ 1); loadB(kt + 1, buf ^ 1); CP_COMMIT(); }

        const uint32_t sb  = smem_u32(smh) + (uint32_t)buf * (BUFF_H * 2);
        const uint32_t AHb = sb;
        const uint32_t ALb = sb + MAT_H * 2;
        const uint32_t BHb = sb + 2 * (MAT_H * 2);
        const uint32_t BLb = sb + 3 * (MAT_H * 2);

        #pragma unroll
        for (int ks = 0; ks < 2; ks++) {
            const int kk = ks * 16;
            const uint32_t aoffb = (uint32_t)((a_off + kk) * 2);
            const uint32_t boffb = (uint32_t)((b_off + kk) * 2);
            #pragma unroll
            for (int ntp = 0; ntp < 2; ntp++) {
                uint32_t bh0, bh1, bh2, bh3, bl0, bl1, bl2, bl3;
                const uint32_t bstep = (uint32_t)(ntp * 16 * PITCH_H * 2);
                LDSM4(bh0, bh1, bh2, bh3, BHb + boffb + bstep);
                LDSM4(bl0, bl1, bl2, bl3, BLb + boffb + bstep);
                #pragma unroll
                for (int mt = 0; mt < 4; mt++) {
                    uint32_t ah0, ah1, ah2, ah3, al0, al1, al2, al3;
                    const uint32_t astep = (uint32_t)(mt * 16 * PITCH_H * 2);
                    LDSM4(ah0, ah1, ah2, ah3, AHb + aoffb + astep);
                    LDSM4(al0, al1, al2, al3, ALb + aoffb + astep);
                    float* d0 = acc[mt][2 * ntp];
                    float* d1 = acc[mt][2 * ntp + 1];
                    mma_f16(d0[0], d0[1], d0[2], d0[3], ah0, ah1, ah2, ah3, bh0, bh1);
                    mma_f16(d1[0], d1[1], d1[2], d1[3], ah0, ah1, ah2, ah3, bh2, bh3);
                    mma_f16(d0[0], d0[1], d0[2], d0[3], ah0, ah1, ah2, ah3, bl0, bl1);
                    mma_f16(d1[0], d1[1], d1[2], d1[3], ah0, ah1, ah2, ah3, bl2, bl3);
                    mma_f16(d0[0], d0[1], d0[2], d0[3], al0, al1, al2, al3, bh0, bh1);
                    mma_f16(d1[0], d1[1], d1[2], d1[3], al0, al1, al2, al3, bh2, bh3);
                }
            }
        }
    }

    // ---------------- epilogue (from registers) ----------------
    const bool even = ((N & 1) == 0);
    #pragma unroll
    for (int mt = 0; mt < 4; mt++) {
        #pragma unroll
        for (int nt = 0; nt < 4; nt++) {
            const int gn = n0 + wn * 32 + nt * 8 + 2 * t;
            if (gn >= N) continue;
            const float b0 = bias[gn];
            const float b1 = (gn + 1 < N) ? bias[gn + 1] : 0.f;
            #pragma unroll
            for (int h = 0; h < 2; h++) {
                const int gm = bm0 + wm * 64 + mt * 16 + g + h * 8;
                float v0 = acc[mt][nt][h * 2 + 0] + b0;
                float v1 = acc[mt][nt][h * 2 + 1] + b1;
                if (HAS_RES) {
                    const float* rp = Res + (long)gm * N + gn;
                    v0 += rp[0];
                    if (gn + 1 < N) v1 += rp[1];
                }
                if (RELU) { v0 = fmaxf(v0, 0.f); v1 = fmaxf(v1, 0.f); }
                if (QKV) {
                    float* dst;
                    if (gn < 256)      dst = Out0 + (long)gm * 256 + gn;
                    else if (gn < 512) dst = Out1 + ((long)chan * M2 + gm) * 256 + (gn - 256);
                    else               dst = Out2 + ((long)chan * M2 + gm) * 256 + (gn - 512);
                    *(float2*)dst = make_float2(v0, v1);
                } else {
                    if (OUT32) {
                        if (even && gn + 1 < N) {
                            *(float2*)(Out0 + (long)gm * N + gn) = make_float2(v0, v1);
                        } else {
                            Out0[(long)gm * N + gn] = v0;
                            if (gn + 1 < N) Out0[(long)gm * N + gn + 1] = v1;
                        }
                    }
                    if (OUT16) {
                        const __half h0 = __float2half_rn(v0), h1 = __float2half_rn(v1);
                        const uint32_t ph = pack2(h0, h1);
                        const uint32_t pl = pack2(__float2half_rn(v0 - __half2float(h0)),
                                                  __float2half_rn(v1 - __half2float(h1)));
                        *(uint32_t*)(O16h + (long)gm * N + gn) = ph;
                        *(uint32_t*)(O16l + (long)gm * N + gn) = pl;
                    }
                }
            }
        }
    }
}

// ---------------- one-shot prep: weight transpose+split, bias pack, state init ----------------
__global__ void prep_kernel(const float* __restrict__ W_in, const float* __restrict__ Wq,
                            const float* __restrict__ Wk, const float* __restrict__ Wv,
                            const float* __restrict__ Wo, const float* __restrict__ Wf1,
                            const float* __restrict__ Wf2, const float* __restrict__ Ws1,
                            const float* __restrict__ W_out,
                            const float* __restrict__ bq, const float* __restrict__ bk,
                            const float* __restrict__ bv)
{
    const int i = blockIdx.x * 256 + threadIdx.x;
    float v; int li;
    __half *dh, *dl;
    if (i < 73728) {            // W_in: K=257 N=256 Kpad=288
        li = i; const int n = li / 288, k = li % 288;
        v = (k < 257) ? W_in[(long)k * 256 + n] : 0.f;
        dh = g_bt_in_hi; dl = g_bt_in_lo;
    } else if (i < 139264) {    // Wq
        li = i - 73728; const int n = li / 256, k = li % 256;
        v = Wq[(long)k * 256 + n];
        dh = g_bt_qkv_hi; dl = g_bt_qkv_lo;
    } else if (i < 204800) {    // Wk
        li = i - 139264; const int n = li / 256, k = li % 256;
        v = Wk[(long)k * 256 + n];
        dh = g_bt_qkv_hi + 65536; dl = g_bt_qkv_lo + 65536;
    } else if (i < 270336) {    // Wv
        li = i - 204800; const int n = li / 256, k = li % 256;
        v = Wv[(long)k * 256 + n];
        dh = g_bt_qkv_hi + 131072; dl = g_bt_qkv_lo + 131072;
    } else if (i < 335872) {    // Wo
        li = i - 270336; const int n = li / 256, k = li % 256;
        v = Wo[(long)k * 256 + n];
        dh = g_bt_o_hi; dl = g_bt_o_lo;
    } else if (i < 466944) {    // Wf1: K=256 N=512
        li = i - 335872; const int n = li / 256, k = li % 256;
        v = Wf1[(long)k * 512 + n];
        dh = g_bt_f1_hi; dl = g_bt_f1_lo;
    } else if (i < 598016) {    // Wf2: K=512 N=256
        li = i - 466944; const int n = li / 512, k = li % 512;
        v = Wf2[(long)k * 256 + n];
        dh = g_bt_f2_hi; dl = g_bt_f2_lo;
    } else if (i < 630784) {    // Ws1: K=256 N=128
        li = i - 598016; const int n = li / 256, k = li % 256;
        v = Ws1[(long)k * 128 + n];
        dh = g_bt_s1_hi; dl = g_bt_s1_lo;
    } else if (i < 729088) {    // W_out: K=256 N=257 Nrows=384
        li = i - 630784; const int n = li / 256, k = li % 256;
        v = (n < 257) ? W_out[(long)k * 257 + n] : 0.f;
        dh = g_bt_out_hi; dl = g_bt_out_lo;
    } else if (i < 729856) {    // bqkv
        const int j = i - 729088;
        g_bqkv[j] = (j < 256) ? bq[j] : ((j < 512) ? bk[j - 256] : bv[j - 512]);
        return;
    } else if (i < 746240) {    // per-row ACT state
        const int r = i - 729856;
        g_cum[r] = 0.f; g_rem[r] = 1.f; g_still[r] = 1.f; g_pc[r] = 0.f;
        if (r == 0) { g_gate[0] = 1.f; g_any[0] = 0; g_done[0] = 0; }
        return;
    } else return;
    const __half h = __float2half_rn(v);
    dh[li] = h;
    dl[li] = __float2half_rn(v - __half2float(h));
}

// ---------------- layernorm: one warp per row of 256, writes fp32 + fp16 hi/lo ----------------
__global__ void ln_kernel(const float* __restrict__ in, const float* __restrict__ g,
                          const float* __restrict__ b, float* __restrict__ out,
                          __half* __restrict__ oh, __half* __restrict__ ol,
                          const float* gate)
{
    if (*gate < 0.5f) return;
    const int r = blockIdx.x * 8 + (threadIdx.x >> 5);
    const int l = threadIdx.x & 31;
    const float* p = in + (long)r * Hz;
    float x[8]; float s = 0.f;
    #pragma unroll
    for (int j = 0; j < 8; j++) { x[j] = p[l + 32 * j]; s += x[j]; }
    #pragma unroll
    for (int o = 16; o; o >>= 1) s += __shfl_xor_sync(0xffffffffu, s, o);
    const float m = s * (1.f / 256.f);
    float vs = 0.f;
    #pragma unroll
    for (int j = 0; j < 8; j++) { const float d = x[j] - m; vs += d * d; }
    #pragma unroll
    for (int o = 16; o; o >>= 1) vs += __shfl_xor_sync(0xffffffffu, vs, o);
    const float inv = 1.f / sqrtf(vs * (1.f / 256.f) + 1e-5f);
    float* q = out + (long)r * Hz;
    #pragma unroll
    for (int j = 0; j < 8; j++) {
        const int c = l + 32 * j;
        const float val = (x[j] - m) * inv * g[c] + b[c];
        q[c] = val;
        const __half h = __float2half_rn(val);
        oh[(long)r * Hz + c] = h;
        ol[(long)r * Hz + c] = __float2half_rn(val - __half2float(h));
    }
}

// ---------------- channel attention: writes ctx as fp16 hi/lo ----------------
__global__ void attn_kernel(const float* __restrict__ q, const float* __restrict__ k,
                            const float* __restrict__ v,
                            __half* __restrict__ ctxh, __half* __restrict__ ctxl,
                            int cc, const float* gate)
{
    if (*gate < 0.5f) return;
    const int wid = threadIdx.x >> 5;
    const int r = blockIdx.x * 2 + (wid >> 2);
    const int w = wid & 3;
    const int l = threadIdx.x & 31;
    const float* qp = q + (long)r * Hz + w * DHz;
    const float q0 = qp[l * 2], q1 = qp[l * 2 + 1];
    float sc[Cz];
    for (int c = 0; c < cc; c++) {
        const float* kp = k + ((long)c * M2 + r) * Hz + w * DHz;
        float p = q0 * kp[l * 2] + q1 * kp[l * 2 + 1];
        #pragma unroll
        for (int o = 16; o; o >>= 1) p += __shfl_xor_sync(0xffffffffu, p, o);
        sc[c] = p * 0.125f;
    }
    float mx = -1e30f;
    for (int c = 0; c < cc; c++) mx = fmaxf(mx, sc[c]);
    float se = 0.f;
    for (int c = 0; c < cc; c++) { sc[c] = expf(sc[c] - mx); se += sc[c]; }
    const float invs = 1.f / se;
    float o0 = 0.f, o1 = 0.f;
    for (int c = 0; c < cc; c++) {
        const float* vp = v + ((long)c * M2 + r) * Hz + w * DHz;
        const float a = sc[c] * invs;
        o0 += a * vp[l * 2]; o1 += a * vp[l * 2 + 1];
    }
    const long off = (long)r * Hz + w * DHz + l * 2;
    const __half h0 = __float2half_rn(o0), h1 = __float2half_rn(o1);
    *(uint32_t*)(ctxh + off) = pack2(h0, h1);
    *(uint32_t*)(ctxl + off) = pack2(__float2half_rn(o0 - __half2float(h0)),
                                     __float2half_rn(o1 - __half2float(h1)));
}

// ---------------- ACT ponder update (gate update folded in) ----------------
__global__ void ponder_kernel(const float* __restrict__ s1, const float* __restrict__ Ws2,
                              const float* __restrict__ bs2, const float* __restrict__ ps_a,
                              const float* __restrict__ ps_b, const float* __restrict__ hh,
                              float* cum, float* rem, float* still, float* pc,
                              float* __restrict__ outacc,
                              int last, int first, float* gate, int* anyflag, int* done)
{
    if (*gate < 0.5f) return;
    const int wid  = threadIdx.x >> 5;
    const int lane = threadIdx.x & 31;
    const int r = blockIdx.x * 8 + wid;

    float p = 0.f;
    if (!last) {
        #pragma unroll
        for (int j = 0; j < 4; j++) {
            const int c = lane + 32 * j;
            p += s1[(long)r * HSz + c] * Ws2[c];
        }
    }
    #pragma unroll
    for (int o = 16; o; o >>= 1) p += __shfl_xor_sync(0xffffffffu, p, o);

    float wgt = 0.f;
    if (lane == 0) {
        float cur;
        if (last) cur = 1.f;
        else {
            const float s = p + bs2[0];
            const float z = (s - ps_a[0]) / (ps_b[0] + 1e-8f);
            cur = 1.f / (1.f + expf(-z));
        }
        const float cm = cum[r], st = still[r], rm = rem[r], p0 = pc[r];
        const float cum_n   = cm + cur * st;
        float pc_n          = p0 + st;
        const float still_n = (cum_n < 1.f - 1e-4f) ? 1.f : 0.f;
        const float rem_n   = rm - cur * still_n;
        pc_n += rem_n * (1.f - still_n);
        wgt = cur * still_n + rm * (1.f - still_n);
        cum[r] = cum_n; rem[r] = rem_n; still[r] = still_n; pc[r] = pc_n;
        if (still_n > 0.5f) *anyflag = 1;
    }
    wgt = __shfl_sync(0xffffffffu, wgt, 0);

    float4* oa = (float4*)(outacc + (long)r * Hz);
    const float4* hp = (const float4*)(hh + (long)r * Hz);
    #pragma unroll
    for (int j = 0; j < 2; j++) {
        const int i = lane * 2 + j;
        const float4 h4 = hp[i];
        if (first) {
            oa[i] = make_float4(h4.x * wgt, h4.y * wgt, h4.z * wgt, h4.w * wgt);
        } else {
            float4 o4 = oa[i];
            o4.x += h4.x * wgt; o4.y += h4.y * wgt;
            o4.z += h4.z * wgt; o4.w += h4.w * wgt;
            oa[i] = o4;
        }
    }

    // last block updates the gate
    __syncthreads();
    if (threadIdx.x == 0) {
        __threadfence();
        const int old = atomicAdd(done, 1);
        if (old == (int)gridDim.x - 1) {
            __threadfence();
            *gate = (*anyflag != 0) ? 1.f : 0.f;
            *anyflag = 0;
            *done = 0;
        }
    }
}

__global__ void pc_out_kernel(float* out, const float* pc)
{
    const int i = blockIdx.x * blockDim.x + threadIdx.x;
    if (i < M2) out[BTF + i] = pc[i];
}

// ---------------- host launch ----------------
static void* symA(const void* s)
{
    void* p = nullptr;
    cudaGetSymbolAddress(&p, s);
    return p;
}

extern "C" void kernel_launch(void* const* d_in, const int* in_sizes, int n_in,
                              void* d_out, int out_size)
{
    const float* x     = (const float*)d_in[0];
    const float* W_in  = (const float*)d_in[1];
    const float* b_in  = (const float*)d_in[2];
    const float* W_out = (const float*)d_in[3];
    const float* b_out = (const float*)d_in[4];
    const float* Wq    = (const float*)d_in[5];
    const float* bq    = (const float*)d_in[6];
    const float* Wk    = (const float*)d_in[7];
    const float* bk    = (const float*)d_in[8];
    const float* Wv    = (const float*)d_in[9];
    const float* bv    = (const float*)d_in[10];
    const float* Wo    = (const float*)d_in[11];
    const float* bo    = (const float*)d_in[12];
    const float* ln1_g = (const float*)d_in[13];
    const float* ln1_b = (const float*)d_in[14];
    const float* Wf1   = (const float*)d_in[15];
    const float* bf1   = (const float*)d_in[16];
    const float* Wf2   = (const float*)d_in[17];
    const float* bf2   = (const float*)d_in[18];
    const float* ln2_g = (const float*)d_in[19];
    const float* ln2_b = (const float*)d_in[20];
    const float* Ws1   = (const float*)d_in[21];
    const float* bs1   = (const float*)d_in[22];
    const float* Ws2   = (const float*)d_in[23];
    const float* bs2   = (const float*)d_in[24];
    const float* ps_a  = (const float*)d_in[25];
    const float* ps_b  = (const float*)d_in[26];
    float* out = (float*)d_out;

    float* p_lin1  = (float*)symA(g_lin1);
    float* p_q     = (float*)symA(g_q);
    float* p_k     = (float*)symA(g_k);
    float* p_v     = (float*)symA(g_v);
    float* p_h1pre = (float*)symA(g_h1pre);
    float* p_h1    = (float*)symA(g_h1);
    float* p_hhpre = (float*)symA(g_hhpre);
    float* p_hh    = (float*)symA(g_hh);
    float* p_s1    = (float*)symA(g_s1);
    float* p_oacc  = (float*)symA(g_outacc);
    float* p_cum   = (float*)symA(g_cum);
    float* p_rem   = (float*)symA(g_rem);
    float* p_still = (float*)symA(g_still);
    float* p_pc    = (float*)symA(g_pc);
    float* p_bqkv  = (float*)symA(g_bqkv);
    float* p_gate  = (float*)symA(g_gate);
    int*   p_any   = (int*)symA(g_any);
    int*   p_done  = (int*)symA(g_done);

    __half* lin1_h = (__half*)symA(g_lin1_h), *lin1_l = (__half*)symA(g_lin1_l);
    __half* ctx_h  = (__half*)symA(g_ctx_h),  *ctx_l  = (__half*)symA(g_ctx_l);
    __half* h1_h   = (__half*)symA(g_h1_h),   *h1_l   = (__half*)symA(g_h1_l);
    __half* f1a_h  = (__half*)symA(g_f1_h),   *f1a_l  = (__half*)symA(g_f1_l);
    __half* hh_h   = (__half*)symA(g_hh_h),   *hh_l   = (__half*)symA(g_hh_l);

    __half* bt_in_h  = (__half*)symA(g_bt_in_hi),  *bt_in_l  = (__half*)symA(g_bt_in_lo);
    __half* bt_qkv_h = (__half*)symA(g_bt_qkv_hi), *bt_qkv_l = (__half*)symA(g_bt_qkv_lo);
    __half* bt_o_h   = (__half*)symA(g_bt_o_hi),   *bt_o_l   = (__half*)symA(g_bt_o_lo);
    __half* bt_f1_h  = (__half*)symA(g_bt_f1_hi),  *bt_f1_l  = (__half*)symA(g_bt_f1_lo);
    __half* bt_f2_h  = (__half*)symA(g_bt_f2_hi),  *bt_f2_l  = (__half*)symA(g_bt_f2_lo);
    __half* bt_s1_h  = (__half*)symA(g_bt_s1_hi),  *bt_s1_l  = (__half*)symA(g_bt_s1_lo);
    __half* bt_out_h = (__half*)symA(g_bt_out_hi), *bt_out_l = (__half*)symA(g_bt_out_lo);

    cudaFuncSetAttribute((const void*)gemm_tc<1, true,  false, false, true,  true >,
                         cudaFuncAttributeMaxDynamicSharedMemorySize, SMEM_DYN);
    cudaFuncSetAttribute((const void*)gemm_tc<2, false, false, true,  true,  false>,
                         cudaFuncAttributeMaxDynamicSharedMemorySize, SMEM_DYN);
    cudaFuncSetAttribute((const void*)gemm_tc<2, false, true,  false, true,  false>,
                         cudaFuncAttributeMaxDynamicSharedMemorySize, SMEM_DYN);
    cudaFuncSetAttribute((const void*)gemm_tc<2, true,  false, false, false, true >,
                         cudaFuncAttributeMaxDynamicSharedMemorySize, SMEM_DYN);
    cudaFuncSetAttribute((const void*)gemm_tc<2, true,  false, false, true,  false>,
                         cudaFuncAttributeMaxDynamicSharedMemorySize, SMEM_DYN);
    cudaFuncSetAttribute((const void*)gemm_tc<0, true,  false, false, true,  false>,
                         cudaFuncAttributeMaxDynamicSharedMemorySize, SMEM_DYN);

    // one-shot prep: weight split + bias pack + ACT state init
    prep_kernel<<<2916, 256>>>(W_in, Wq, Wk, Wv, Wo, Wf1, Wf2, Ws1, W_out, bq, bk, bv);

    const dim3 gN256(2, 128), gN768(6, 128), gN512(4, 128), gN128(1, 128), gN257(3, 128);

    for (int ci = 0; ci < Cz; ci++) {
        // lin1 = relu(x[:,ci] @ W_in + b_in) -> fp32 + fp16 hi/lo
        gemm_tc<1, true, false, false, true, true><<<gN256, 256, SMEM_DYN>>>(
            x, nullptr, nullptr, bt_in_h, bt_in_l, b_in, nullptr,
            p_lin1, nullptr, nullptr, lin1_h, lin1_l,
            256, 257, 288, 9, ci, p_gate);
        // q / k[ci] / v[ci]
        gemm_tc<2, false, false, true, true, false><<<gN768, 256, SMEM_DYN>>>(
            nullptr, lin1_h, lin1_l, bt_qkv_h, bt_qkv_l, p_bqkv, nullptr,
            p_q, p_k, p_v, nullptr, nullptr,
            768, 256, 256, 8, ci, p_gate);
        attn_kernel<<<8192, 256>>>(p_q, p_k, p_v, ctx_h, ctx_l, ci + 1, p_gate);
        // h1pre = lin1 + ctx@Wo + bo
        gemm_tc<2, false, true, false, true, false><<<gN256, 256, SMEM_DYN>>>(
            nullptr, ctx_h, ctx_l, bt_o_h, bt_o_l, bo, p_lin1,
            p_h1pre, nullptr, nullptr, nullptr, nullptr,
            256, 256, 256, 8, 0, p_gate);
        ln_kernel<<<2048, 256>>>(p_h1pre, ln1_g, ln1_b, p_h1, h1_h, h1_l, p_gate);
        // f1 = relu(h1@Wf1+bf1)  (fp16 hi/lo only)
        gemm_tc<2, true, false, false, false, true><<<gN512, 256, SMEM_DYN>>>(
            nullptr, h1_h, h1_l, bt_f1_h, bt_f1_l, bf1, nullptr,
            nullptr, nullptr, nullptr, f1a_h, f1a_l,
            512, 256, 256, 8, 0, p_gate);
        // hhpre = h1 + f1@Wf2 + bf2
        gemm_tc<2, false, true, false, true, false><<<gN256, 256, SMEM_DYN>>>(
            nullptr, f1a_h, f1a_l, bt_f2_h, bt_f2_l, bf2, p_h1,
            p_hhpre, nullptr, nullptr, nullptr, nullptr,
            256, 512, 512, 16, 0, p_gate);
        ln_kernel<<<2048, 256>>>(p_hhpre, ln2_g, ln2_b, p_hh, hh_h, hh_l, p_gate);
        if (ci < Cz - 1) {
            gemm_tc<2, true, false, false, true, false><<<gN128, 256, SMEM_DYN>>>(
                nullptr, hh_h, hh_l, bt_s1_h, bt_s1_l, bs1, nullptr,
                p_s1, nullptr, nullptr, nullptr, nullptr,
                128, 256, 256, 8, 0, p_gate);
        }
        ponder_kernel<<<2048, 256>>>(p_s1, Ws2, bs2, ps_a, ps_b, p_hh,
                                     p_cum, p_rem, p_still, p_pc, p_oacc,
                                     (ci == Cz - 1) ? 1 : 0, (ci == 0) ? 1 : 0,
                                     p_gate, p_any, p_done);
    }

    // encoder_out = relu(out_acc @ W_out + b_out)
    gemm_tc<0, true, false, false, true, false><<<gN257, 256, SMEM_DYN>>>(
        p_oacc, nullptr, nullptr, bt_out_h, bt_out_l, b_out, nullptr,
        out, nullptr, nullptr, nullptr, nullptr,
        257, 256, 256, 8, 0, nullptr);
    pc_out_kernel<<<64, 256>>>(out, p_pc);
}